// round 11
// baseline (speedup 1.0000x reference)
#include <cuda_runtime.h>
#include <cuda_fp16.h>
#include <math.h>
#include <stdint.h>

#define HD    200
#define POOL  16
#define TLEN  4096
#define NPH   3200   // POOL*HD
#define K1PAD 416    // pad of 2*HD=400 to mult of 32
#define K2PAD 224    // pad of HD=200 to mult of 32

// ------------------------------------------------------------------
// Static device scratch
// ------------------------------------------------------------------
__device__ __align__(16) __half g_UT[TLEN][K1PAD];        // A1 [t][k]
__device__ __align__(16) __half g_B1[2][K1PAD][NPH];      // B1 [k][n]
__device__ __align__(16) __half g_B2[2][K2PAD][NPH];      // B2 [k][n]
__device__ __align__(16) __half g_m1[2][TLEN][K2PAD];     // A2 [t][k]
__device__ __align__(16) __half g_PU[2][TLEN][NPH];       // fp16, 52 MB
__device__ __align__(16) float g_m2[2][TLEN][HD];
__device__ __align__(16) float g_b2T[2][NPH];
__device__ __align__(16) float g_prT[2][NPH];
__device__ __align__(16) float g_x[800];                  // gathered [u_s, u_e]
__device__ float g_g[4 * HD];
__device__ float g_hB[2][HD];
__device__ float g_cB[2][HD];
__device__ float g_r[2][HD];
__device__ unsigned long long g_slot[2][2];

// ------------------------------------------------------------------
// helpers
// ------------------------------------------------------------------
__device__ __forceinline__ uint32_t smem_u32(const void* p) {
    uint32_t a;
    asm("{ .reg .u64 t; cvta.to.shared.u64 t, %1; cvt.u32.u64 %0, t; }" : "=r"(a) : "l"(p));
    return a;
}
__device__ __forceinline__ void cp16(uint32_t dst, const void* src) {
    asm volatile("cp.async.cg.shared.global [%0], [%1], 16;" :: "r"(dst), "l"(src));
}
#define CP_COMMIT() asm volatile("cp.async.commit_group;" ::: "memory")
#define CP_WAIT1()  asm volatile("cp.async.wait_group 1;" ::: "memory")

__device__ __forceinline__ void ldsm4(uint32_t* r, uint32_t addr) {
    asm volatile("ldmatrix.sync.aligned.m8n8.x4.shared.b16 {%0,%1,%2,%3}, [%4];"
                 : "=r"(r[0]), "=r"(r[1]), "=r"(r[2]), "=r"(r[3]) : "r"(addr));
}
__device__ __forceinline__ void ldsm4t(uint32_t* r, uint32_t addr) {
    asm volatile("ldmatrix.sync.aligned.m8n8.x4.trans.shared.b16 {%0,%1,%2,%3}, [%4];"
                 : "=r"(r[0]), "=r"(r[1]), "=r"(r[2]), "=r"(r[3]) : "r"(addr));
}
__device__ __forceinline__ void mma_f16(float* c, const uint32_t* a, const uint32_t* b) {
    asm volatile(
        "mma.sync.aligned.m16n8k16.row.col.f32.f16.f16.f32 "
        "{%0,%1,%2,%3}, {%4,%5,%6,%7}, {%8,%9}, {%0,%1,%2,%3};"
        : "+f"(c[0]), "+f"(c[1]), "+f"(c[2]), "+f"(c[3])
        : "r"(a[0]), "r"(a[1]), "r"(a[2]), "r"(a[3]), "r"(b[0]), "r"(b[1]));
}
__device__ __forceinline__ float sigm(float x) { return 1.0f / (1.0f + expf(-x)); }
__device__ __forceinline__ unsigned long long enc_max(float v, int t) {
    uint32_t u = __float_as_uint(v);
    u = (u & 0x80000000u) ? ~u : (u | 0x80000000u);
    return ((unsigned long long)u << 32) | (uint32_t)(TLEN - 1 - t);
}
__device__ __forceinline__ int dec_idx(unsigned long long s) {
    return TLEN - 1 - (int)(uint32_t)(s & 0xFFFFFFFFull);
}
__device__ __forceinline__ float dot4(float4 a, float4 b) {
    return a.x * b.x + a.y * b.y + a.z * b.z + a.w * b.w;
}

// ------------------------------------------------------------------
// prep: tiled transposes (all global accesses coalesced)
// ------------------------------------------------------------------
__global__ void prep_UT(const float* __restrict__ U) {
    __shared__ float tile[32][33];
    int k0 = blockIdx.x * 32, t0 = blockIdx.y * 32;
    int tx = threadIdx.x, ty0 = threadIdx.y;
#pragma unroll
    for (int i = 0; i < 4; i++) {
        int tk = ty0 * 4 + i;
        int k = k0 + tk;
        tile[tk][tx] = (k < 2 * HD) ? U[(size_t)k * TLEN + t0 + tx] : 0.f;
    }
    __syncthreads();
#pragma unroll
    for (int i = 0; i < 4; i++) {
        int tt = ty0 * 4 + i;
        g_UT[t0 + tt][k0 + tx] = __float2half(tile[tx][tt]);
    }
}

__global__ void prep_B1(const float* __restrict__ W1a, const float* __restrict__ W1b) {
    __shared__ float tile[32][33];
    int net = blockIdx.z;
    int k0 = blockIdx.x * 32, n0 = blockIdx.y * 32;
    int tx = threadIdx.x, ty0 = threadIdx.y;
    const float* W1 = net ? W1b : W1a;
#pragma unroll
    for (int i = 0; i < 4; i++) {
        int ty = ty0 * 4 + i;
        int n = n0 + ty;
        int h = n >> 4, p = n & 15;
        int k = k0 + tx;
        tile[ty][tx] = (k < 2 * HD) ? W1[(size_t)(p * HD + h) * 600 + k] : 0.f;
    }
    __syncthreads();
#pragma unroll
    for (int i = 0; i < 4; i++) {
        int ty = ty0 * 4 + i;
        g_B1[net][k0 + ty][n0 + tx] = __float2half(tile[tx][ty]);
    }
}

__global__ void prep_B2(const float* __restrict__ W2a, const float* __restrict__ W2b) {
    __shared__ float tile[32][33];
    int net = blockIdx.z;
    int k0 = blockIdx.x * 32, n0 = blockIdx.y * 32;
    int tx = threadIdx.x, ty0 = threadIdx.y;
    const float* W2 = net ? W2b : W2a;
#pragma unroll
    for (int i = 0; i < 4; i++) {
        int ty = ty0 * 4 + i;
        int n = n0 + ty;
        int h = n >> 4, p = n & 15;
        int k = k0 + tx;
        tile[ty][tx] = (k < HD) ? W2[(size_t)(p * HD + h) * HD + k] : 0.f;
    }
    __syncthreads();
#pragma unroll
    for (int i = 0; i < 4; i++) {
        int ty = ty0 * 4 + i;
        g_B2[net][k0 + ty][n0 + tx] = __float2half(tile[tx][ty]);
    }
}

__global__ void prep_misc(const float* __restrict__ b2a, const float* __restrict__ b2b,
                          const float* __restrict__ h0,  const float* __restrict__ c0) {
    int idx0 = blockIdx.x * blockDim.x + threadIdx.x;
    int stride = gridDim.x * blockDim.x;
    for (int i = idx0; i < 2 * NPH; i += stride) {
        int net = i / NPH, n = i - net * NPH;
        int h = n >> 4, p = n & 15;
        const float* b2 = net ? b2b : b2a;
        g_b2T[net][n] = b2[p * HD + h];
    }
    for (int i = idx0; i < 2 * TLEN * (K2PAD - HD); i += stride) {
        int net = i / (TLEN * (K2PAD - HD));
        int rem = i - net * (TLEN * (K2PAD - HD));
        int t = rem / (K2PAD - HD);
        int k = HD + (rem - t * (K2PAD - HD));
        g_m1[net][t][k] = __float2half(0.f);
    }
    if (idx0 < HD) { g_hB[1][idx0] = h0[idx0]; g_cB[1][idx0] = c0[idx0]; }
}

// ------------------------------------------------------------------
// mma.sync GEMM: C[t][n] = sum_k A[t][k]*B[k][n]; single fp16 both sides.
// MODE 0: A=UT (K=416), B=B1 -> fp16 store to g_PU
// MODE 1: A=m1 (K=224), B=B2 -> +b2T, max over p -> g_m2[t][h]
// Block tile 256(m) x 128(n), 512 threads, 16 warps (8m x 2n), warp 32x64,
// K-chunk 32, 3-stage cp.async pipeline (wait_group 1).
// ------------------------------------------------------------------
#define A_ROW_B   80
#define A_STG_B   20480              // 256 rows * 80B
#define B_ROW_B   272
#define B_STG_B   8704
#define OFF_B     61440              // 3 * A_STG_B
#define GEMM_SMEM (61440 + 26112)    // + 3 * B_STG_B = 87552

template <int MODE>
__global__ void __launch_bounds__(512) gemm_mma() {
    extern __shared__ char smem[];
    const int tid    = threadIdx.x;
    const int lane   = tid & 31;
    const int wid    = tid >> 5;
    const int warp_m = wid & 7;      // 8 m-quadrants of 32 rows
    const int warp_n = wid >> 3;     // 2 n-halves of 64 cols
    const int net    = blockIdx.z;
    const int m0     = blockIdx.x * 256;
    const int n0     = blockIdx.y * 128;
    const int KPAD   = (MODE == 0) ? K1PAD : K2PAD;
    const int NC     = KPAD / 32;

    const __half* __restrict__ Ap = (MODE == 0) ? &g_UT[0][0] : &g_m1[net][0][0];
    const __half* __restrict__ Bp = (MODE == 0) ? &g_B1[net][0][0] : &g_B2[net][0][0];

    const uint32_t sb = smem_u32(smem);

    // A: 256 rows x 4 16B-chunks = 1024 chunks / 512 thr = 2 each (paired)
    const int arow = tid >> 1;           // 0..255
    const int aq   = (tid & 1) * 2;      // chunk {0,1} or {2,3}
    // B: 32 rows x 16 16B-chunks = 512 chunks / 512 thr = 1 each
    const int brow = tid >> 4;           // 0..31
    const int bq   = tid & 15;           // 0..15

    auto load_stage = [&](int stage, int kc) {
        const uint32_t as = sb + stage * A_STG_B + arow * A_ROW_B + aq * 16;
        const __half* ah = Ap + (size_t)(m0 + arow) * KPAD + kc + aq * 8;
        cp16(as,      ah);
        cp16(as + 16, ah + 8);
        const uint32_t bs = sb + OFF_B + stage * B_STG_B + brow * B_ROW_B + bq * 16;
        const __half* bg = Bp + (size_t)(kc + brow) * NPH + n0 + bq * 8;
        cp16(bs, bg);
    };

    float acc[2][8][4];
#pragma unroll
    for (int i = 0; i < 2; i++)
#pragma unroll
        for (int j = 0; j < 8; j++)
#pragma unroll
            for (int q = 0; q < 4; q++) acc[i][j][q] = 0.f;

    const int l15 = lane & 15;
    const int l16 = (lane >> 4) * 8;
    const uint32_t aBase = sb + (warp_m * 32 + l15) * A_ROW_B + l16 * 2;
    const uint32_t bBase = sb + OFF_B + l15 * B_ROW_B + (warp_n * 64 + l16) * 2;

    load_stage(0, 0);
    CP_COMMIT();
    load_stage(1, 32);
    CP_COMMIT();

    for (int c = 0; c < NC; c++) {
        CP_WAIT1();
        __syncthreads();
        const int stg = c % 3;
        const uint32_t aS = aBase + stg * A_STG_B;
        const uint32_t bS = bBase + stg * B_STG_B;
#pragma unroll
        for (int s = 0; s < 2; s++) {
            uint32_t ah[2][4];
#pragma unroll
            for (int i = 0; i < 2; i++)
                ldsm4(ah[i], aS + i * 16 * A_ROW_B + s * 32);
#pragma unroll
            for (int half = 0; half < 2; half++) {
                uint32_t bb[4][2];
#pragma unroll
                for (int pr = 0; pr < 2; pr++) {
                    uint32_t r[4];
                    ldsm4t(r, bS + s * 16 * B_ROW_B + (half * 2 + pr) * 32);
                    bb[pr * 2][0] = r[0]; bb[pr * 2][1] = r[1];
                    bb[pr * 2 + 1][0] = r[2]; bb[pr * 2 + 1][1] = r[3];
                }
#pragma unroll
                for (int i = 0; i < 2; i++)
#pragma unroll
                    for (int j = 0; j < 4; j++)
                        mma_f16(acc[i][half * 4 + j], ah[i], bb[j]);
            }
        }
        if (c + 2 < NC) { load_stage((c + 2) % 3, (c + 2) * 32); }
        CP_COMMIT();
    }

    const int g4 = lane >> 2;
    const int t2 = (lane & 3) * 2;
    if (MODE == 0) {
        __half* C = &g_PU[net][0][0];
#pragma unroll
        for (int i = 0; i < 2; i++) {
            int r0 = m0 + warp_m * 32 + i * 16 + g4;
#pragma unroll
            for (int j = 0; j < 8; j++) {
                int col = n0 + warp_n * 64 + j * 8 + t2;
                *(__half2*)&C[(size_t)r0 * NPH + col] =
                    __floats2half2_rn(acc[i][j][0], acc[i][j][1]);
                *(__half2*)&C[(size_t)(r0 + 8) * NPH + col] =
                    __floats2half2_rn(acc[i][j][2], acc[i][j][3]);
            }
        }
    } else {
        float b2v[8][2];
#pragma unroll
        for (int j = 0; j < 8; j++) {
            int col = n0 + warp_n * 64 + j * 8 + t2;
            b2v[j][0] = __ldg(&g_b2T[net][col]);
            b2v[j][1] = __ldg(&g_b2T[net][col + 1]);
        }
        const int h0i = (n0 + warp_n * 64) >> 4;
#pragma unroll
        for (int i = 0; i < 2; i++) {
#pragma unroll
            for (int hh = 0; hh < 4; hh++) {
                float mlo = -3.4e38f, mhi = -3.4e38f;
#pragma unroll
                for (int jj = 0; jj < 2; jj++) {
                    int j = hh * 2 + jj;
                    mlo = fmaxf(mlo, fmaxf(acc[i][j][0] + b2v[j][0], acc[i][j][1] + b2v[j][1]));
                    mhi = fmaxf(mhi, fmaxf(acc[i][j][2] + b2v[j][0], acc[i][j][3] + b2v[j][1]));
                }
                mlo = fmaxf(mlo, __shfl_xor_sync(0xffffffffu, mlo, 1));
                mlo = fmaxf(mlo, __shfl_xor_sync(0xffffffffu, mlo, 2));
                mhi = fmaxf(mhi, __shfl_xor_sync(0xffffffffu, mhi, 1));
                mhi = fmaxf(mhi, __shfl_xor_sync(0xffffffffu, mhi, 2));
                if ((lane & 3) == 0) {
                    int row = m0 + warp_m * 32 + i * 16 + g4;
                    g_m2[net][row][h0i + hh]     = mlo;
                    g_m2[net][row + 8][h0i + hh] = mhi;
                }
            }
        }
    }
}

// ------------------------------------------------------------------
// gather: decode s,e; gather U columns into g_x; reset this-iter slots
// ------------------------------------------------------------------
__global__ void gather_kernel(const float* __restrict__ U, int it) {
    int tid = threadIdx.x;
    int s = (it == 0) ? 0 : dec_idx(g_slot[(it + 1) & 1][0]);
    int e = (it == 0) ? 0 : dec_idx(g_slot[(it + 1) & 1][1]);
    if (tid == 0) {
        g_slot[it & 1][0] = 0ull;
        g_slot[it & 1][1] = 0ull;
    }
    for (int j = tid; j < 800; j += 256)
        g_x[j] = (j < 400) ? U[(size_t)j * TLEN + s] : U[(size_t)(j - 400) * TLEN + e];
}

// ------------------------------------------------------------------
// LSTM gates: 8 rows/block, 1 warp per row, float4 dots (x from g_x)
// ------------------------------------------------------------------
__global__ void lstm_gates(const float* __restrict__ W_ih, const float* __restrict__ W_hh,
                           const float* __restrict__ b_ih, const float* __restrict__ b_hh,
                           int it) {
    __shared__ __align__(16) float xs[800];
    __shared__ __align__(16) float hs[HD];
    int tid = threadIdx.x;
    for (int j = tid; j < 800; j += 256) xs[j] = g_x[j];
    const float* hprev = g_hB[(it + 1) & 1];
    for (int j = tid; j < HD; j += 256) hs[j] = hprev[j];
    __syncthreads();
    int row = blockIdx.x * 8 + (tid >> 5);
    int lane = tid & 31;
    const float4* w4  = (const float4*)&W_ih[(size_t)row * 800];
    const float4* xs4 = (const float4*)xs;
    float acc = 0.f;
    for (int k = lane; k < 200; k += 32) acc += dot4(w4[k], xs4[k]);
    const float4* wh4 = (const float4*)&W_hh[(size_t)row * HD];
    const float4* hs4 = (const float4*)hs;
    if (lane < 25) {
        acc += dot4(wh4[lane], hs4[lane]);
        acc += dot4(wh4[lane + 25], hs4[lane + 25]);
    }
#pragma unroll
    for (int o = 16; o; o >>= 1) acc += __shfl_xor_sync(0xffffffffu, acc, o);
    if (lane == 0) g_g[row] = acc + b_ih[row] + b_hh[row];
}

// ------------------------------------------------------------------
// fused LSTM update + r = tanh(WD @ [h_new, u_s, u_e]); x from g_x
// ------------------------------------------------------------------
__global__ void r_kernel(const float* __restrict__ WDa, const float* __restrict__ WDb,
                         int it) {
    __shared__ __align__(16) float vs[1000];
    int tid = threadIdx.x;
    if (tid < HD) {
        float gi = g_g[tid], gf = g_g[HD + tid], gg = g_g[2 * HD + tid], go = g_g[3 * HD + tid];
        float c = sigm(gf) * g_cB[(it + 1) & 1][tid] + sigm(gi) * tanhf(gg);
        float h = sigm(go) * tanhf(c);
        vs[tid] = h;
        if (blockIdx.x == 0) { g_cB[it & 1][tid] = c; g_hB[it & 1][tid] = h; }
    }
    for (int j = tid; j < 800; j += 256) vs[HD + j] = g_x[j];
    __syncthreads();
    int row = blockIdx.x * 8 + (tid >> 5);
    int lane = tid & 31;
    int net = row / HD;
    int rr = row - net * HD;
    const float* WD = net ? WDb : WDa;
    const float4* w4  = (const float4*)&WD[(size_t)rr * 1000];
    const float4* vs4 = (const float4*)vs;
    float acc = 0.f;
    for (int k = lane; k < 250; k += 32) acc += dot4(w4[k], vs4[k]);
#pragma unroll
    for (int o = 16; o; o >>= 1) acc += __shfl_xor_sync(0xffffffffu, acc, o);
    if (lane == 0) g_r[net][rr] = tanhf(acc);
}

// ------------------------------------------------------------------
// prT[net][h*16+p] = W1r[p][h]@r + b1[p][h]; 4 outputs per warp
// grid 200 blocks x 256 thr
// ------------------------------------------------------------------
__global__ void pr_kernel(const float* __restrict__ W1a, const float* __restrict__ W1b,
                          const float* __restrict__ b1a, const float* __restrict__ b1b) {
    int warp = blockIdx.x * 8 + (threadIdx.x >> 5);
    int lane = threadIdx.x & 31;
#pragma unroll
    for (int u = 0; u < 4; u++) {
        int o = warp * 4 + u;                 // 0..6399
        int net = o / NPH;
        int n = o - net * NPH;
        int h = n >> 4, p = n & 15;
        const float* W1 = net ? W1b : W1a;
        const float* b1 = net ? b1b : b1a;
        const float4* w4 = (const float4*)&W1[(size_t)(p * HD + h) * 600 + 400];
        const float4* r4 = (const float4*)g_r[net];
        float acc = 0.f;
        if (lane < 25) {
            acc += dot4(w4[lane], r4[lane]);
            acc += dot4(w4[lane + 25], r4[lane + 25]);
        }
#pragma unroll
        for (int o2 = 16; o2; o2 >>= 1) acc += __shfl_xor_sync(0xffffffffu, acc, o2);
        if (lane == 0) g_prT[net][n] = acc + b1[p * HD + h];
    }
}

// ------------------------------------------------------------------
// m1[t][h] = max_p(PU[t][h*16+p] + prT[h*16+p]) -> single fp16
// ------------------------------------------------------------------
__global__ void m1_kernel() {
    int net = blockIdx.y;
    int t0 = blockIdx.x * 16;
    int tid = threadIdx.x;
    for (int item = tid; item < 16 * HD; item += 256) {
        int tt = item / HD, h = item - tt * HD;
        int t = t0 + tt;
        const uint4* pu4 = (const uint4*)&g_PU[net][t][h << 4];
        const float4* pr = (const float4*)&g_prT[net][h << 4];
        uint4 v0 = pu4[0], v1 = pu4[1];
        const __half2* a = (const __half2*)&v0;
        const __half2* b = (const __half2*)&v1;
        float m = -3.4e38f;
#pragma unroll
        for (int q = 0; q < 2; q++) {
            float4 pv = pr[q];
            float2 a0 = __half22float2(a[q * 2]);
            float2 a1 = __half22float2(a[q * 2 + 1]);
            m = fmaxf(m, fmaxf(fmaxf(a0.x + pv.x, a0.y + pv.y), fmaxf(a1.x + pv.z, a1.y + pv.w)));
        }
#pragma unroll
        for (int q = 0; q < 2; q++) {
            float4 pv = pr[2 + q];
            float2 a0 = __half22float2(b[q * 2]);
            float2 a1 = __half22float2(b[q * 2 + 1]);
            m = fmaxf(m, fmaxf(fmaxf(a0.x + pv.x, a0.y + pv.y), fmaxf(a1.x + pv.z, a1.y + pv.w)));
        }
        g_m1[net][t][h] = __float2half(m);
    }
}

// ------------------------------------------------------------------
// scores + fused argmax: 64 t per block, 512 threads
// ------------------------------------------------------------------
#define SCORE_SMEM ((64 * 408 + 16 * 401 + 128) * 4)
__global__ void __launch_bounds__(512) score_kernel(
        const float* __restrict__ W3a, const float* __restrict__ W3b,
        const float* __restrict__ b3a, const float* __restrict__ b3b,
        float* __restrict__ out, int it, int maxI) {
    extern __shared__ float sm[];
    float* ms  = sm;                 // [64][408]
    float* w3s = sm + 64 * 408;      // [16][401]
    float* bmx = w3s + 16 * 401;     // [64]
    int*   bmi = (int*)(bmx + 64);   // [64]
    int net = blockIdx.y;
    int t0 = blockIdx.x * 64;
    int tid = threadIdx.x;
    const float* W3 = net ? W3b : W3a;
    for (int idx = tid; idx < 6400; idx += 512) {
        int p = idx / 400, d = idx - p * 400;
        w3s[p * 401 + d] = W3[p * 400 + d];
    }
    for (int idx = tid; idx < 64 * HD; idx += 512) {
        int tt = idx / HD, h = idx - tt * HD;
        int t = t0 + tt;
        ms[tt * 408 + h] = __half2float(g_m1[net][t][h]);
        ms[tt * 408 + 200 + h] = g_m2[net][t][h];
    }
    __syncthreads();
    int grp = tid >> 4, p = tid & 15;
    float bias = (net ? b3b : b3a)[p];
    const float* w3r = &w3s[p * 401];
#pragma unroll
    for (int rep = 0; rep < 2; rep++) {
        int tt = grp + rep * 32;
        float acc = bias;
        const float* msr = &ms[tt * 408];
#pragma unroll 4
        for (int d = 0; d < 400; d++) acc = fmaf(msr[d], w3r[d], acc);
#pragma unroll
        for (int o = 8; o; o >>= 1) acc = fmaxf(acc, __shfl_xor_sync(0xffffffffu, acc, o));
        if (p == 0) {
            out[((size_t)net * maxI + it) * TLEN + t0 + tt] = acc;
            bmx[tt] = acc;
            bmi[tt] = t0 + tt;
        }
    }
    __syncthreads();
    if (tid == 0) {
        float bv = bmx[0]; int bi = bmi[0];
        for (int q = 1; q < 64; q++) {
            if (bmx[q] > bv) { bv = bmx[q]; bi = bmi[q]; }
        }
        atomicMax(&g_slot[it & 1][net], enc_max(bv, bi));
    }
}

__global__ void finalize_kernel(float* __restrict__ out, int maxI) {
    out[(size_t)2 * maxI * TLEN + 0] = (float)dec_idx(g_slot[(maxI - 1) & 1][0]);
    out[(size_t)2 * maxI * TLEN + 1] = (float)dec_idx(g_slot[(maxI - 1) & 1][1]);
}

// ------------------------------------------------------------------
// launch
// ------------------------------------------------------------------
extern "C" void kernel_launch(void* const* d_in, const int* in_sizes, int n_in,
                              void* d_out, int out_size) {
    const float* U    = (const float*)d_in[0];
    const float* h0   = (const float*)d_in[2];
    const float* c0   = (const float*)d_in[3];
    const float* W_ih = (const float*)d_in[4];
    const float* W_hh = (const float*)d_in[5];
    const float* b_ih = (const float*)d_in[6];
    const float* b_hh = (const float*)d_in[7];
    const float* WD_a = (const float*)d_in[8];
    const float* W1_a = (const float*)d_in[9];
    const float* b1_a = (const float*)d_in[10];
    const float* W2_a = (const float*)d_in[11];
    const float* b2_a = (const float*)d_in[12];
    const float* W3_a = (const float*)d_in[13];
    const float* b3_a = (const float*)d_in[14];
    const float* WD_b = (const float*)d_in[15];
    const float* W1_b = (const float*)d_in[16];
    const float* b1_b = (const float*)d_in[17];
    const float* W2_b = (const float*)d_in[18];
    const float* b2_b = (const float*)d_in[19];
    const float* W3_b = (const float*)d_in[20];
    const float* b3_b = (const float*)d_in[21];
    float* out = (float*)d_out;

    int maxI = out_size / (2 * TLEN);
    if (maxI < 1) maxI = 1;
    int write_se = (out_size >= 2 * maxI * TLEN + 2) ? 1 : 0;

    cudaFuncSetAttribute(gemm_mma<0>, cudaFuncAttributeMaxDynamicSharedMemorySize, GEMM_SMEM);
    cudaFuncSetAttribute(gemm_mma<1>, cudaFuncAttributeMaxDynamicSharedMemorySize, GEMM_SMEM);
    cudaFuncSetAttribute(score_kernel, cudaFuncAttributeMaxDynamicSharedMemorySize, SCORE_SMEM);

    prep_UT<<<dim3(K1PAD / 32, TLEN / 32), dim3(32, 8)>>>(U);
    prep_B1<<<dim3(K1PAD / 32, NPH / 32, 2), dim3(32, 8)>>>(W1_a, W1_b);
    prep_B2<<<dim3(K2PAD / 32, NPH / 32, 2), dim3(32, 8)>>>(W2_a, W2_b);
    prep_misc<<<128, 256>>>(b2_a, b2_b, h0, c0);
    gemm_mma<0><<<dim3(TLEN / 256, NPH / 128, 2), 512, GEMM_SMEM>>>();

    for (int it = 0; it < maxI; it++) {
        gather_kernel<<<1, 256>>>(U, it);
        lstm_gates<<<100, 256>>>(W_ih, W_hh, b_ih, b_hh, it);
        r_kernel<<<50, 256>>>(WD_a, WD_b, it);
        pr_kernel<<<200, 256>>>(W1_a, W1_b, b1_a, b1_b);
        m1_kernel<<<dim3(TLEN / 16, 2), 256>>>();
        gemm_mma<1><<<dim3(TLEN / 256, NPH / 128, 2), 512, GEMM_SMEM>>>();
        score_kernel<<<dim3(TLEN / 64, 2), 512, SCORE_SMEM>>>(W3_a, W3_b, b3_a, b3_b, out, it, maxI);
    }
    if (write_se) finalize_kernel<<<1, 1>>>(out, maxI);
}

// round 12
// speedup vs baseline: 1.0704x; 1.0704x over previous
#include <cuda_runtime.h>
#include <cuda_fp16.h>
#include <math.h>
#include <stdint.h>

#define HD    200
#define POOL  16
#define TLEN  4096
#define NPH   3200   // POOL*HD
#define K1PAD 416    // pad of 2*HD=400 to mult of 32
#define K2PAD 224    // pad of HD=200 to mult of 32

// ------------------------------------------------------------------
// Static device scratch
// ------------------------------------------------------------------
__device__ __align__(16) __half g_UT[TLEN][K1PAD];        // A1 [t][k]
__device__ __align__(16) __half g_B1[2][K1PAD][NPH];      // B1 [k][n]
__device__ __align__(16) __half g_B2[2][K2PAD][NPH];      // B2 [k][n]
__device__ __align__(16) __half g_m1[2][TLEN][K2PAD];     // A2 [t][k]
__device__ __align__(16) __half g_PU[2][TLEN][NPH];       // fp16, 52 MB
__device__ __align__(16) float g_m2[2][TLEN][HD];
__device__ __align__(16) float g_b2T[2][NPH];
__device__ __align__(16) float g_prT[2][NPH];
__device__ __align__(16) float g_x[800];                  // gathered [u_s, u_e]
__device__ float g_g[4 * HD];
__device__ float g_hB[2][HD];
__device__ float g_cB[2][HD];
__device__ float g_r[2][HD];
__device__ unsigned long long g_slot[2][2];

// ------------------------------------------------------------------
// helpers
// ------------------------------------------------------------------
__device__ __forceinline__ uint32_t smem_u32(const void* p) {
    uint32_t a;
    asm("{ .reg .u64 t; cvta.to.shared.u64 t, %1; cvt.u32.u64 %0, t; }" : "=r"(a) : "l"(p));
    return a;
}
__device__ __forceinline__ void cp16(uint32_t dst, const void* src) {
    asm volatile("cp.async.cg.shared.global [%0], [%1], 16;" :: "r"(dst), "l"(src));
}
#define CP_COMMIT() asm volatile("cp.async.commit_group;" ::: "memory")
#define CP_WAIT1()  asm volatile("cp.async.wait_group 1;" ::: "memory")

__device__ __forceinline__ void ldsm4(uint32_t* r, uint32_t addr) {
    asm volatile("ldmatrix.sync.aligned.m8n8.x4.shared.b16 {%0,%1,%2,%3}, [%4];"
                 : "=r"(r[0]), "=r"(r[1]), "=r"(r[2]), "=r"(r[3]) : "r"(addr));
}
__device__ __forceinline__ void ldsm4t(uint32_t* r, uint32_t addr) {
    asm volatile("ldmatrix.sync.aligned.m8n8.x4.trans.shared.b16 {%0,%1,%2,%3}, [%4];"
                 : "=r"(r[0]), "=r"(r[1]), "=r"(r[2]), "=r"(r[3]) : "r"(addr));
}
__device__ __forceinline__ void mma_f16(float* c, const uint32_t* a, const uint32_t* b) {
    asm volatile(
        "mma.sync.aligned.m16n8k16.row.col.f32.f16.f16.f32 "
        "{%0,%1,%2,%3}, {%4,%5,%6,%7}, {%8,%9}, {%0,%1,%2,%3};"
        : "+f"(c[0]), "+f"(c[1]), "+f"(c[2]), "+f"(c[3])
        : "r"(a[0]), "r"(a[1]), "r"(a[2]), "r"(a[3]), "r"(b[0]), "r"(b[1]));
}
__device__ __forceinline__ float sigm(float x) { return 1.0f / (1.0f + expf(-x)); }
__device__ __forceinline__ unsigned long long enc_max(float v, int t) {
    uint32_t u = __float_as_uint(v);
    u = (u & 0x80000000u) ? ~u : (u | 0x80000000u);
    return ((unsigned long long)u << 32) | (uint32_t)(TLEN - 1 - t);
}
__device__ __forceinline__ int dec_idx(unsigned long long s) {
    return TLEN - 1 - (int)(uint32_t)(s & 0xFFFFFFFFull);
}
__device__ __forceinline__ float dot4(float4 a, float4 b) {
    return a.x * b.x + a.y * b.y + a.z * b.z + a.w * b.w;
}

// ------------------------------------------------------------------
// prep: tiled transposes (all global accesses coalesced)
// ------------------------------------------------------------------
__global__ void prep_UT(const float* __restrict__ U) {
    __shared__ float tile[32][33];
    int k0 = blockIdx.x * 32, t0 = blockIdx.y * 32;
    int tx = threadIdx.x, ty0 = threadIdx.y;
#pragma unroll
    for (int i = 0; i < 4; i++) {
        int tk = ty0 * 4 + i;
        int k = k0 + tk;
        tile[tk][tx] = (k < 2 * HD) ? U[(size_t)k * TLEN + t0 + tx] : 0.f;
    }
    __syncthreads();
#pragma unroll
    for (int i = 0; i < 4; i++) {
        int tt = ty0 * 4 + i;
        g_UT[t0 + tt][k0 + tx] = __float2half(tile[tx][tt]);
    }
}

__global__ void prep_B1(const float* __restrict__ W1a, const float* __restrict__ W1b) {
    __shared__ float tile[32][33];
    int net = blockIdx.z;
    int k0 = blockIdx.x * 32, n0 = blockIdx.y * 32;
    int tx = threadIdx.x, ty0 = threadIdx.y;
    const float* W1 = net ? W1b : W1a;
#pragma unroll
    for (int i = 0; i < 4; i++) {
        int ty = ty0 * 4 + i;
        int n = n0 + ty;
        int h = n >> 4, p = n & 15;
        int k = k0 + tx;
        tile[ty][tx] = (k < 2 * HD) ? W1[(size_t)(p * HD + h) * 600 + k] : 0.f;
    }
    __syncthreads();
#pragma unroll
    for (int i = 0; i < 4; i++) {
        int ty = ty0 * 4 + i;
        g_B1[net][k0 + ty][n0 + tx] = __float2half(tile[tx][ty]);
    }
}

__global__ void prep_B2(const float* __restrict__ W2a, const float* __restrict__ W2b) {
    __shared__ float tile[32][33];
    int net = blockIdx.z;
    int k0 = blockIdx.x * 32, n0 = blockIdx.y * 32;
    int tx = threadIdx.x, ty0 = threadIdx.y;
    const float* W2 = net ? W2b : W2a;
#pragma unroll
    for (int i = 0; i < 4; i++) {
        int ty = ty0 * 4 + i;
        int n = n0 + ty;
        int h = n >> 4, p = n & 15;
        int k = k0 + tx;
        tile[ty][tx] = (k < HD) ? W2[(size_t)(p * HD + h) * HD + k] : 0.f;
    }
    __syncthreads();
#pragma unroll
    for (int i = 0; i < 4; i++) {
        int ty = ty0 * 4 + i;
        g_B2[net][k0 + ty][n0 + tx] = __float2half(tile[tx][ty]);
    }
}

__global__ void prep_misc(const float* __restrict__ b2a, const float* __restrict__ b2b,
                          const float* __restrict__ h0,  const float* __restrict__ c0) {
    int idx0 = blockIdx.x * blockDim.x + threadIdx.x;
    int stride = gridDim.x * blockDim.x;
    for (int i = idx0; i < 2 * NPH; i += stride) {
        int net = i / NPH, n = i - net * NPH;
        int h = n >> 4, p = n & 15;
        const float* b2 = net ? b2b : b2a;
        g_b2T[net][n] = b2[p * HD + h];
    }
    for (int i = idx0; i < 2 * TLEN * (K2PAD - HD); i += stride) {
        int net = i / (TLEN * (K2PAD - HD));
        int rem = i - net * (TLEN * (K2PAD - HD));
        int t = rem / (K2PAD - HD);
        int k = HD + (rem - t * (K2PAD - HD));
        g_m1[net][t][k] = __float2half(0.f);
    }
    if (idx0 < HD) { g_hB[1][idx0] = h0[idx0]; g_cB[1][idx0] = c0[idx0]; }
}

// ------------------------------------------------------------------
// mma.sync GEMM (round-10 proven shape): C[t][n] = sum_k A[t][k]*B[k][n]
// MODE 0: A=UT (K=416), B=B1 -> fp16 store to g_PU
// MODE 1: A=m1 (K=224), B=B2 -> +b2T, max over p -> g_m2[t][h]
// Block tile 128x128, 256 threads, 8 warps (4m x 2n), warp 32x64,
// K-chunk 32, 3-stage cp.async pipeline (wait_group 1). 2 CTAs/SM.
// ------------------------------------------------------------------
#define A_ROW_B   80
#define A_STG_B   10240
#define B_ROW_B   272
#define B_STG_B   8704
#define OFF_B     30720              // 3 * A_STG_B
#define GEMM_SMEM (30720 + 26112)    // 3 A stages + 3 B stages = 56832

template <int MODE>
__global__ void __launch_bounds__(256) gemm_mma() {
    extern __shared__ char smem[];
    const int tid    = threadIdx.x;
    const int lane   = tid & 31;
    const int wid    = tid >> 5;
    const int warp_m = wid & 3;
    const int warp_n = wid >> 2;
    const int net    = blockIdx.z;
    const int m0     = blockIdx.x * 128;
    const int n0     = blockIdx.y * 128;
    const int KPAD   = (MODE == 0) ? K1PAD : K2PAD;
    const int NC     = KPAD / 32;

    const __half* __restrict__ Ap = (MODE == 0) ? &g_UT[0][0] : &g_m1[net][0][0];
    const __half* __restrict__ Bp = (MODE == 0) ? &g_B1[net][0][0] : &g_B2[net][0][0];

    const uint32_t sb = smem_u32(smem);

    const int arow = tid >> 1;
    const int aq   = (tid & 1) * 2;
    const int brow = tid >> 3;
    const int bq   = tid & 7;

    auto load_stage = [&](int stage, int kc) {
        const uint32_t as = sb + stage * A_STG_B + arow * A_ROW_B + aq * 16;
        const __half* ah = Ap + (size_t)(m0 + arow) * KPAD + kc + aq * 8;
        cp16(as,      ah);
        cp16(as + 16, ah + 8);
        const uint32_t bs = sb + OFF_B + stage * B_STG_B + brow * B_ROW_B + bq * 32;
        const __half* bg = Bp + (size_t)(kc + brow) * NPH + n0 + bq * 16;
        cp16(bs,      bg);
        cp16(bs + 16, bg + 8);
    };

    float acc[2][8][4];
#pragma unroll
    for (int i = 0; i < 2; i++)
#pragma unroll
        for (int j = 0; j < 8; j++)
#pragma unroll
            for (int q = 0; q < 4; q++) acc[i][j][q] = 0.f;

    const int l15 = lane & 15;
    const int l16 = (lane >> 4) * 8;
    const uint32_t aBase = sb + (warp_m * 32 + l15) * A_ROW_B + l16 * 2;
    const uint32_t bBase = sb + OFF_B + l15 * B_ROW_B + (warp_n * 64 + l16) * 2;

    load_stage(0, 0);
    CP_COMMIT();
    load_stage(1, 32);
    CP_COMMIT();

    for (int c = 0; c < NC; c++) {
        CP_WAIT1();
        __syncthreads();
        const int stg = c % 3;
        const uint32_t aS = aBase + stg * A_STG_B;
        const uint32_t bS = bBase + stg * B_STG_B;
#pragma unroll
        for (int s = 0; s < 2; s++) {
            uint32_t ah[2][4];
#pragma unroll
            for (int i = 0; i < 2; i++)
                ldsm4(ah[i], aS + i * 16 * A_ROW_B + s * 32);
#pragma unroll
            for (int half = 0; half < 2; half++) {
                uint32_t bb[4][2];
#pragma unroll
                for (int pr = 0; pr < 2; pr++) {
                    uint32_t r[4];
                    ldsm4t(r, bS + s * 16 * B_ROW_B + (half * 2 + pr) * 32);
                    bb[pr * 2][0] = r[0]; bb[pr * 2][1] = r[1];
                    bb[pr * 2 + 1][0] = r[2]; bb[pr * 2 + 1][1] = r[3];
                }
#pragma unroll
                for (int i = 0; i < 2; i++)
#pragma unroll
                    for (int j = 0; j < 4; j++)
                        mma_f16(acc[i][half * 4 + j], ah[i], bb[j]);
            }
        }
        if (c + 2 < NC) { load_stage((c + 2) % 3, (c + 2) * 32); }
        CP_COMMIT();
    }

    const int g4 = lane >> 2;
    const int t2 = (lane & 3) * 2;
    if (MODE == 0) {
        __half* C = &g_PU[net][0][0];
#pragma unroll
        for (int i = 0; i < 2; i++) {
            int r0 = m0 + warp_m * 32 + i * 16 + g4;
#pragma unroll
            for (int j = 0; j < 8; j++) {
                int col = n0 + warp_n * 64 + j * 8 + t2;
                *(__half2*)&C[(size_t)r0 * NPH + col] =
                    __floats2half2_rn(acc[i][j][0], acc[i][j][1]);
                *(__half2*)&C[(size_t)(r0 + 8) * NPH + col] =
                    __floats2half2_rn(acc[i][j][2], acc[i][j][3]);
            }
        }
    } else {
        float b2v[8][2];
#pragma unroll
        for (int j = 0; j < 8; j++) {
            int col = n0 + warp_n * 64 + j * 8 + t2;
            b2v[j][0] = __ldg(&g_b2T[net][col]);
            b2v[j][1] = __ldg(&g_b2T[net][col + 1]);
        }
        const int h0i = (n0 + warp_n * 64) >> 4;
#pragma unroll
        for (int i = 0; i < 2; i++) {
#pragma unroll
            for (int hh = 0; hh < 4; hh++) {
                float mlo = -3.4e38f, mhi = -3.4e38f;
#pragma unroll
                for (int jj = 0; jj < 2; jj++) {
                    int j = hh * 2 + jj;
                    mlo = fmaxf(mlo, fmaxf(acc[i][j][0] + b2v[j][0], acc[i][j][1] + b2v[j][1]));
                    mhi = fmaxf(mhi, fmaxf(acc[i][j][2] + b2v[j][0], acc[i][j][3] + b2v[j][1]));
                }
                mlo = fmaxf(mlo, __shfl_xor_sync(0xffffffffu, mlo, 1));
                mlo = fmaxf(mlo, __shfl_xor_sync(0xffffffffu, mlo, 2));
                mhi = fmaxf(mhi, __shfl_xor_sync(0xffffffffu, mhi, 1));
                mhi = fmaxf(mhi, __shfl_xor_sync(0xffffffffu, mhi, 2));
                if ((lane & 3) == 0) {
                    int row = m0 + warp_m * 32 + i * 16 + g4;
                    g_m2[net][row][h0i + hh]     = mlo;
                    g_m2[net][row + 8][h0i + hh] = mhi;
                }
            }
        }
    }
}

// ------------------------------------------------------------------
// gather: decode s,e; gather U columns into g_x; reset this-iter slots
// ------------------------------------------------------------------
__global__ void gather_kernel(const float* __restrict__ U, int it) {
    int tid = threadIdx.x;
    int s = (it == 0) ? 0 : dec_idx(g_slot[(it + 1) & 1][0]);
    int e = (it == 0) ? 0 : dec_idx(g_slot[(it + 1) & 1][1]);
    if (tid == 0) {
        g_slot[it & 1][0] = 0ull;
        g_slot[it & 1][1] = 0ull;
    }
    for (int j = tid; j < 800; j += 256)
        g_x[j] = (j < 400) ? U[(size_t)j * TLEN + s] : U[(size_t)(j - 400) * TLEN + e];
}

// ------------------------------------------------------------------
// LSTM gates: 8 rows/block, 1 warp per row, float4 dots (x from g_x)
// ------------------------------------------------------------------
__global__ void lstm_gates(const float* __restrict__ W_ih, const float* __restrict__ W_hh,
                           const float* __restrict__ b_ih, const float* __restrict__ b_hh,
                           int it) {
    __shared__ __align__(16) float xs[800];
    __shared__ __align__(16) float hs[HD];
    int tid = threadIdx.x;
    for (int j = tid; j < 800; j += 256) xs[j] = g_x[j];
    const float* hprev = g_hB[(it + 1) & 1];
    for (int j = tid; j < HD; j += 256) hs[j] = hprev[j];
    __syncthreads();
    int row = blockIdx.x * 8 + (tid >> 5);
    int lane = tid & 31;
    const float4* w4  = (const float4*)&W_ih[(size_t)row * 800];
    const float4* xs4 = (const float4*)xs;
    float acc = 0.f;
    for (int k = lane; k < 200; k += 32) acc += dot4(w4[k], xs4[k]);
    const float4* wh4 = (const float4*)&W_hh[(size_t)row * HD];
    const float4* hs4 = (const float4*)hs;
    if (lane < 25) {
        acc += dot4(wh4[lane], hs4[lane]);
        acc += dot4(wh4[lane + 25], hs4[lane + 25]);
    }
#pragma unroll
    for (int o = 16; o; o >>= 1) acc += __shfl_xor_sync(0xffffffffu, acc, o);
    if (lane == 0) g_g[row] = acc + b_ih[row] + b_hh[row];
}

// ------------------------------------------------------------------
// fused LSTM update + r = tanh(WD @ [h_new, u_s, u_e]); x from g_x
// ------------------------------------------------------------------
__global__ void r_kernel(const float* __restrict__ WDa, const float* __restrict__ WDb,
                         int it) {
    __shared__ __align__(16) float vs[1000];
    int tid = threadIdx.x;
    if (tid < HD) {
        float gi = g_g[tid], gf = g_g[HD + tid], gg = g_g[2 * HD + tid], go = g_g[3 * HD + tid];
        float c = sigm(gf) * g_cB[(it + 1) & 1][tid] + sigm(gi) * tanhf(gg);
        float h = sigm(go) * tanhf(c);
        vs[tid] = h;
        if (blockIdx.x == 0) { g_cB[it & 1][tid] = c; g_hB[it & 1][tid] = h; }
    }
    for (int j = tid; j < 800; j += 256) vs[HD + j] = g_x[j];
    __syncthreads();
    int row = blockIdx.x * 8 + (tid >> 5);
    int lane = tid & 31;
    int net = row / HD;
    int rr = row - net * HD;
    const float* WD = net ? WDb : WDa;
    const float4* w4  = (const float4*)&WD[(size_t)rr * 1000];
    const float4* vs4 = (const float4*)vs;
    float acc = 0.f;
    for (int k = lane; k < 250; k += 32) acc += dot4(w4[k], vs4[k]);
#pragma unroll
    for (int o = 16; o; o >>= 1) acc += __shfl_xor_sync(0xffffffffu, acc, o);
    if (lane == 0) g_r[net][rr] = tanhf(acc);
}

// ------------------------------------------------------------------
// prT[net][h*16+p] = W1r[p][h]@r + b1[p][h]; 4 outputs per warp
// ------------------------------------------------------------------
__global__ void pr_kernel(const float* __restrict__ W1a, const float* __restrict__ W1b,
                          const float* __restrict__ b1a, const float* __restrict__ b1b) {
    int warp = blockIdx.x * 8 + (threadIdx.x >> 5);
    int lane = threadIdx.x & 31;
#pragma unroll
    for (int u = 0; u < 4; u++) {
        int o = warp * 4 + u;                 // 0..6399
        int net = o / NPH;
        int n = o - net * NPH;
        int h = n >> 4, p = n & 15;
        const float* W1 = net ? W1b : W1a;
        const float* b1 = net ? b1b : b1a;
        const float4* w4 = (const float4*)&W1[(size_t)(p * HD + h) * 600 + 400];
        const float4* r4 = (const float4*)g_r[net];
        float acc = 0.f;
        if (lane < 25) {
            acc += dot4(w4[lane], r4[lane]);
            acc += dot4(w4[lane + 25], r4[lane + 25]);
        }
#pragma unroll
        for (int o2 = 16; o2; o2 >>= 1) acc += __shfl_xor_sync(0xffffffffu, acc, o2);
        if (lane == 0) g_prT[net][n] = acc + b1[p * HD + h];
    }
}

// ------------------------------------------------------------------
// m1[t][h] = max_p(PU[t][h*16+p] + prT[h*16+p]) -> single fp16
// ------------------------------------------------------------------
__global__ void m1_kernel() {
    int net = blockIdx.y;
    int t0 = blockIdx.x * 16;
    int tid = threadIdx.x;
    for (int item = tid; item < 16 * HD; item += 256) {
        int tt = item / HD, h = item - tt * HD;
        int t = t0 + tt;
        const uint4* pu4 = (const uint4*)&g_PU[net][t][h << 4];
        const float4* pr = (const float4*)&g_prT[net][h << 4];
        uint4 v0 = pu4[0], v1 = pu4[1];
        const __half2* a = (const __half2*)&v0;
        const __half2* b = (const __half2*)&v1;
        float m = -3.4e38f;
#pragma unroll
        for (int q = 0; q < 2; q++) {
            float4 pv = pr[q];
            float2 a0 = __half22float2(a[q * 2]);
            float2 a1 = __half22float2(a[q * 2 + 1]);
            m = fmaxf(m, fmaxf(fmaxf(a0.x + pv.x, a0.y + pv.y), fmaxf(a1.x + pv.z, a1.y + pv.w)));
        }
#pragma unroll
        for (int q = 0; q < 2; q++) {
            float4 pv = pr[2 + q];
            float2 a0 = __half22float2(b[q * 2]);
            float2 a1 = __half22float2(b[q * 2 + 1]);
            m = fmaxf(m, fmaxf(fmaxf(a0.x + pv.x, a0.y + pv.y), fmaxf(a1.x + pv.z, a1.y + pv.w)));
        }
        g_m1[net][t][h] = __float2half(m);
    }
}

// ------------------------------------------------------------------
// scores + fused argmax: 64 t per block, 512 threads
// ------------------------------------------------------------------
#define SCORE_SMEM ((64 * 408 + 16 * 401 + 128) * 4)
__global__ void __launch_bounds__(512) score_kernel(
        const float* __restrict__ W3a, const float* __restrict__ W3b,
        const float* __restrict__ b3a, const float* __restrict__ b3b,
        float* __restrict__ out, int it, int maxI) {
    extern __shared__ float sm[];
    float* ms  = sm;                 // [64][408]
    float* w3s = sm + 64 * 408;      // [16][401]
    float* bmx = w3s + 16 * 401;     // [64]
    int*   bmi = (int*)(bmx + 64);   // [64]
    int net = blockIdx.y;
    int t0 = blockIdx.x * 64;
    int tid = threadIdx.x;
    const float* W3 = net ? W3b : W3a;
    for (int idx = tid; idx < 6400; idx += 512) {
        int p = idx / 400, d = idx - p * 400;
        w3s[p * 401 + d] = W3[p * 400 + d];
    }
    for (int idx = tid; idx < 64 * HD; idx += 512) {
        int tt = idx / HD, h = idx - tt * HD;
        int t = t0 + tt;
        ms[tt * 408 + h] = __half2float(g_m1[net][t][h]);
        ms[tt * 408 + 200 + h] = g_m2[net][t][h];
    }
    __syncthreads();
    int grp = tid >> 4, p = tid & 15;
    float bias = (net ? b3b : b3a)[p];
    const float* w3r = &w3s[p * 401];
#pragma unroll
    for (int rep = 0; rep < 2; rep++) {
        int tt = grp + rep * 32;
        float acc = bias;
        const float* msr = &ms[tt * 408];
#pragma unroll 4
        for (int d = 0; d < 400; d++) acc = fmaf(msr[d], w3r[d], acc);
#pragma unroll
        for (int o = 8; o; o >>= 1) acc = fmaxf(acc, __shfl_xor_sync(0xffffffffu, acc, o));
        if (p == 0) {
            out[((size_t)net * maxI + it) * TLEN + t0 + tt] = acc;
            bmx[tt] = acc;
            bmi[tt] = t0 + tt;
        }
    }
    __syncthreads();
    if (tid == 0) {
        float bv = bmx[0]; int bi = bmi[0];
        for (int q = 1; q < 64; q++) {
            if (bmx[q] > bv) { bv = bmx[q]; bi = bmi[q]; }
        }
        atomicMax(&g_slot[it & 1][net], enc_max(bv, bi));
    }
}

__global__ void finalize_kernel(float* __restrict__ out, int maxI) {
    out[(size_t)2 * maxI * TLEN + 0] = (float)dec_idx(g_slot[(maxI - 1) & 1][0]);
    out[(size_t)2 * maxI * TLEN + 1] = (float)dec_idx(g_slot[(maxI - 1) & 1][1]);
}

// ------------------------------------------------------------------
// launch
// ------------------------------------------------------------------
extern "C" void kernel_launch(void* const* d_in, const int* in_sizes, int n_in,
                              void* d_out, int out_size) {
    const float* U    = (const float*)d_in[0];
    const float* h0   = (const float*)d_in[2];
    const float* c0   = (const float*)d_in[3];
    const float* W_ih = (const float*)d_in[4];
    const float* W_hh = (const float*)d_in[5];
    const float* b_ih = (const float*)d_in[6];
    const float* b_hh = (const float*)d_in[7];
    const float* WD_a = (const float*)d_in[8];
    const float* W1_a = (const float*)d_in[9];
    const float* b1_a = (const float*)d_in[10];
    const float* W2_a = (const float*)d_in[11];
    const float* b2_a = (const float*)d_in[12];
    const float* W3_a = (const float*)d_in[13];
    const float* b3_a = (const float*)d_in[14];
    const float* WD_b = (const float*)d_in[15];
    const float* W1_b = (const float*)d_in[16];
    const float* b1_b = (const float*)d_in[17];
    const float* W2_b = (const float*)d_in[18];
    const float* b2_b = (const float*)d_in[19];
    const float* W3_b = (const float*)d_in[20];
    const float* b3_b = (const float*)d_in[21];
    float* out = (float*)d_out;

    int maxI = out_size / (2 * TLEN);
    if (maxI < 1) maxI = 1;
    int write_se = (out_size >= 2 * maxI * TLEN + 2) ? 1 : 0;

    cudaFuncSetAttribute(gemm_mma<0>, cudaFuncAttributeMaxDynamicSharedMemorySize, GEMM_SMEM);
    cudaFuncSetAttribute(gemm_mma<1>, cudaFuncAttributeMaxDynamicSharedMemorySize, GEMM_SMEM);
    cudaFuncSetAttribute(score_kernel, cudaFuncAttributeMaxDynamicSharedMemorySize, SCORE_SMEM);

    prep_UT<<<dim3(K1PAD / 32, TLEN / 32), dim3(32, 8)>>>(U);
    prep_B1<<<dim3(K1PAD / 32, NPH / 32, 2), dim3(32, 8)>>>(W1_a, W1_b);
    prep_B2<<<dim3(K2PAD / 32, NPH / 32, 2), dim3(32, 8)>>>(W2_a, W2_b);
    prep_misc<<<128, 256>>>(b2_a, b2_b, h0, c0);
    gemm_mma<0><<<dim3(TLEN / 128, NPH / 128, 2), 256, GEMM_SMEM>>>();

    for (int it = 0; it < maxI; it++) {
        gather_kernel<<<1, 256>>>(U, it);
        lstm_gates<<<100, 256>>>(W_ih, W_hh, b_ih, b_hh, it);
        r_kernel<<<50, 256>>>(WD_a, WD_b, it);
        pr_kernel<<<200, 256>>>(W1_a, W1_b, b1_a, b1_b);
        m1_kernel<<<dim3(TLEN / 16, 2), 256>>>();
        gemm_mma<1><<<dim3(TLEN / 128, NPH / 128, 2), 256, GEMM_SMEM>>>();
        score_kernel<<<dim3(TLEN / 64, 2), 512, SCORE_SMEM>>>(W3_a, W3_b, b3_a, b3_b, out, it, maxI);
    }
    if (write_se) finalize_kernel<<<1, 1>>>(out, maxI);
}

// round 13
// speedup vs baseline: 1.0743x; 1.0036x over previous
#include <cuda_runtime.h>
#include <cuda_fp16.h>
#include <math.h>
#include <stdint.h>

#define HD    200
#define POOL  16
#define TLEN  4096
#define NPH   3200   // POOL*HD
#define K1PAD 416    // pad of 2*HD=400 to mult of 32
#define K2PAD 224    // pad of HD=200 to mult of 32

// ------------------------------------------------------------------
// Static device scratch
// ------------------------------------------------------------------
__device__ __align__(16) __half g_UT[TLEN][K1PAD];        // A1 [t][k]
__device__ __align__(16) __half g_B1[2][K1PAD][NPH];      // B1 [k][n]
__device__ __align__(16) __half g_B2[2][K2PAD][NPH];      // B2 [k][n]
__device__ __align__(16) __half g_m1[2][TLEN][K2PAD];     // A2 [t][k]
__device__ __align__(16) __half g_PU[2][TLEN][NPH];       // fp16, 52 MB
__device__ __align__(16) float g_m2[2][TLEN][HD];
__device__ __align__(16) float g_b2T[2][NPH];
__device__ __align__(16) float g_prT[2][NPH];
__device__ float g_g[4 * HD];
__device__ float g_hB[2][HD];
__device__ float g_cB[2][HD];
__device__ float g_r[2][HD];
__device__ unsigned long long g_slot[2][2];

// ------------------------------------------------------------------
// helpers
// ------------------------------------------------------------------
__device__ __forceinline__ uint32_t smem_u32(const void* p) {
    uint32_t a;
    asm("{ .reg .u64 t; cvta.to.shared.u64 t, %1; cvt.u32.u64 %0, t; }" : "=r"(a) : "l"(p));
    return a;
}
__device__ __forceinline__ void cp16(uint32_t dst, const void* src) {
    asm volatile("cp.async.cg.shared.global [%0], [%1], 16;" :: "r"(dst), "l"(src));
}
#define CP_COMMIT() asm volatile("cp.async.commit_group;" ::: "memory")
#define CP_WAIT2()  asm volatile("cp.async.wait_group 2;" ::: "memory")

__device__ __forceinline__ void ldsm4(uint32_t* r, uint32_t addr) {
    asm volatile("ldmatrix.sync.aligned.m8n8.x4.shared.b16 {%0,%1,%2,%3}, [%4];"
                 : "=r"(r[0]), "=r"(r[1]), "=r"(r[2]), "=r"(r[3]) : "r"(addr));
}
__device__ __forceinline__ void ldsm4t(uint32_t* r, uint32_t addr) {
    asm volatile("ldmatrix.sync.aligned.m8n8.x4.trans.shared.b16 {%0,%1,%2,%3}, [%4];"
                 : "=r"(r[0]), "=r"(r[1]), "=r"(r[2]), "=r"(r[3]) : "r"(addr));
}
__device__ __forceinline__ void mma_f16(float* c, const uint32_t* a, const uint32_t* b) {
    asm volatile(
        "mma.sync.aligned.m16n8k16.row.col.f32.f16.f16.f32 "
        "{%0,%1,%2,%3}, {%4,%5,%6,%7}, {%8,%9}, {%0,%1,%2,%3};"
        : "+f"(c[0]), "+f"(c[1]), "+f"(c[2]), "+f"(c[3])
        : "r"(a[0]), "r"(a[1]), "r"(a[2]), "r"(a[3]), "r"(b[0]), "r"(b[1]));
}
__device__ __forceinline__ float sigm(float x) { return 1.0f / (1.0f + expf(-x)); }
__device__ __forceinline__ unsigned long long enc_max(float v, int t) {
    uint32_t u = __float_as_uint(v);
    u = (u & 0x80000000u) ? ~u : (u | 0x80000000u);
    return ((unsigned long long)u << 32) | (uint32_t)(TLEN - 1 - t);
}
__device__ __forceinline__ int dec_idx(unsigned long long s) {
    return TLEN - 1 - (int)(uint32_t)(s & 0xFFFFFFFFull);
}
__device__ __forceinline__ float dot4(float4 a, float4 b) {
    return a.x * b.x + a.y * b.y + a.z * b.z + a.w * b.w;
}

// ------------------------------------------------------------------
// prep: tiled transposes (all global accesses coalesced)
// ------------------------------------------------------------------
__global__ void prep_UT(const float* __restrict__ U) {
    __shared__ float tile[32][33];
    int k0 = blockIdx.x * 32, t0 = blockIdx.y * 32;
    int tx = threadIdx.x, ty0 = threadIdx.y;
#pragma unroll
    for (int i = 0; i < 4; i++) {
        int tk = ty0 * 4 + i;
        int k = k0 + tk;
        tile[tk][tx] = (k < 2 * HD) ? U[(size_t)k * TLEN + t0 + tx] : 0.f;
    }
    __syncthreads();
#pragma unroll
    for (int i = 0; i < 4; i++) {
        int tt = ty0 * 4 + i;
        g_UT[t0 + tt][k0 + tx] = __float2half(tile[tx][tt]);
    }
}

__global__ void prep_B1(const float* __restrict__ W1a, const float* __restrict__ W1b) {
    __shared__ float tile[32][33];
    int net = blockIdx.z;
    int k0 = blockIdx.x * 32, n0 = blockIdx.y * 32;
    int tx = threadIdx.x, ty0 = threadIdx.y;
    const float* W1 = net ? W1b : W1a;
#pragma unroll
    for (int i = 0; i < 4; i++) {
        int ty = ty0 * 4 + i;
        int n = n0 + ty;
        int h = n >> 4, p = n & 15;
        int k = k0 + tx;
        tile[ty][tx] = (k < 2 * HD) ? W1[(size_t)(p * HD + h) * 600 + k] : 0.f;
    }
    __syncthreads();
#pragma unroll
    for (int i = 0; i < 4; i++) {
        int ty = ty0 * 4 + i;
        g_B1[net][k0 + ty][n0 + tx] = __float2half(tile[tx][ty]);
    }
}

__global__ void prep_B2(const float* __restrict__ W2a, const float* __restrict__ W2b) {
    __shared__ float tile[32][33];
    int net = blockIdx.z;
    int k0 = blockIdx.x * 32, n0 = blockIdx.y * 32;
    int tx = threadIdx.x, ty0 = threadIdx.y;
    const float* W2 = net ? W2b : W2a;
#pragma unroll
    for (int i = 0; i < 4; i++) {
        int ty = ty0 * 4 + i;
        int n = n0 + ty;
        int h = n >> 4, p = n & 15;
        int k = k0 + tx;
        tile[ty][tx] = (k < HD) ? W2[(size_t)(p * HD + h) * HD + k] : 0.f;
    }
    __syncthreads();
#pragma unroll
    for (int i = 0; i < 4; i++) {
        int ty = ty0 * 4 + i;
        g_B2[net][k0 + ty][n0 + tx] = __float2half(tile[tx][ty]);
    }
}

__global__ void prep_misc(const float* __restrict__ b2a, const float* __restrict__ b2b,
                          const float* __restrict__ h0,  const float* __restrict__ c0) {
    int idx0 = blockIdx.x * blockDim.x + threadIdx.x;
    int stride = gridDim.x * blockDim.x;
    for (int i = idx0; i < 2 * NPH; i += stride) {
        int net = i / NPH, n = i - net * NPH;
        int h = n >> 4, p = n & 15;
        const float* b2 = net ? b2b : b2a;
        g_b2T[net][n] = b2[p * HD + h];
    }
    for (int i = idx0; i < 2 * TLEN * (K2PAD - HD); i += stride) {
        int net = i / (TLEN * (K2PAD - HD));
        int rem = i - net * (TLEN * (K2PAD - HD));
        int t = rem / (K2PAD - HD);
        int k = HD + (rem - t * (K2PAD - HD));
        g_m1[net][t][k] = __float2half(0.f);
    }
    if (idx0 < HD) { g_hB[1][idx0] = h0[idx0]; g_cB[1][idx0] = c0[idx0]; }
}

// ------------------------------------------------------------------
// mma.sync GEMM: C[t][n] = sum_k A[t][k]*B[k][n]; single fp16 both sides.
// MODE 0: A=UT (K=416), B=B1 -> fp16 store to g_PU
// MODE 1: A=m1 (K=224), B=B2 -> +b2T, max over p -> g_m2[t][h]
// Block tile 128x128, 256 threads, 8 warps (4m x 2n), warp 32x64,
// K-chunk 32, 4-stage cp.async pipeline (wait_group 2). 2 CTAs/SM.
// ------------------------------------------------------------------
#define A_ROW_B   80
#define A_STG_B   10240
#define B_ROW_B   272
#define B_STG_B   8704
#define OFF_B     40960              // 4 * A_STG_B
#define GEMM_SMEM (40960 + 34816)    // 4 A stages + 4 B stages = 75776

template <int MODE>
__global__ void __launch_bounds__(256) gemm_mma() {
    extern __shared__ char smem[];
    const int tid    = threadIdx.x;
    const int lane   = tid & 31;
    const int wid    = tid >> 5;
    const int warp_m = wid & 3;
    const int warp_n = wid >> 2;
    const int net    = blockIdx.z;
    const int m0     = blockIdx.x * 128;
    const int n0     = blockIdx.y * 128;
    const int KPAD   = (MODE == 0) ? K1PAD : K2PAD;
    const int NC     = KPAD / 32;

    const __half* __restrict__ Ap = (MODE == 0) ? &g_UT[0][0] : &g_m1[net][0][0];
    const __half* __restrict__ Bp = (MODE == 0) ? &g_B1[net][0][0] : &g_B2[net][0][0];

    const uint32_t sb = smem_u32(smem);

    const int arow = tid >> 1;
    const int aq   = (tid & 1) * 2;
    const int brow = tid >> 3;
    const int bq   = tid & 7;

    auto load_stage = [&](int stage, int kc) {
        const uint32_t as = sb + stage * A_STG_B + arow * A_ROW_B + aq * 16;
        const __half* ah = Ap + (size_t)(m0 + arow) * KPAD + kc + aq * 8;
        cp16(as,      ah);
        cp16(as + 16, ah + 8);
        const uint32_t bs = sb + OFF_B + stage * B_STG_B + brow * B_ROW_B + bq * 32;
        const __half* bg = Bp + (size_t)(kc + brow) * NPH + n0 + bq * 16;
        cp16(bs,      bg);
        cp16(bs + 16, bg + 8);
    };

    float acc[2][8][4];
#pragma unroll
    for (int i = 0; i < 2; i++)
#pragma unroll
        for (int j = 0; j < 8; j++)
#pragma unroll
            for (int q = 0; q < 4; q++) acc[i][j][q] = 0.f;

    const int l15 = lane & 15;
    const int l16 = (lane >> 4) * 8;
    const uint32_t aBase = sb + (warp_m * 32 + l15) * A_ROW_B + l16 * 2;
    const uint32_t bBase = sb + OFF_B + l15 * B_ROW_B + (warp_n * 64 + l16) * 2;

    load_stage(0, 0);
    CP_COMMIT();
    load_stage(1, 32);
    CP_COMMIT();
    load_stage(2, 64);
    CP_COMMIT();

    for (int c = 0; c < NC; c++) {
        CP_WAIT2();               // group c complete (<=2 groups still in flight)
        __syncthreads();
        const int stg = c & 3;
        const uint32_t aS = aBase + stg * A_STG_B;
        const uint32_t bS = bBase + stg * B_STG_B;
#pragma unroll
        for (int s = 0; s < 2; s++) {
            uint32_t ah[2][4];
#pragma unroll
            for (int i = 0; i < 2; i++)
                ldsm4(ah[i], aS + i * 16 * A_ROW_B + s * 32);
#pragma unroll
            for (int half = 0; half < 2; half++) {
                uint32_t bb[4][2];
#pragma unroll
                for (int pr = 0; pr < 2; pr++) {
                    uint32_t r[4];
                    ldsm4t(r, bS + s * 16 * B_ROW_B + (half * 2 + pr) * 32);
                    bb[pr * 2][0] = r[0]; bb[pr * 2][1] = r[1];
                    bb[pr * 2 + 1][0] = r[2]; bb[pr * 2 + 1][1] = r[3];
                }
#pragma unroll
                for (int i = 0; i < 2; i++)
#pragma unroll
                    for (int j = 0; j < 4; j++)
                        mma_f16(acc[i][half * 4 + j], ah[i], bb[j]);
            }
        }
        if (c + 3 < NC) { load_stage((c + 3) & 3, (c + 3) * 32); }
        CP_COMMIT();              // one group per iteration keeps counts aligned
    }

    const int g4 = lane >> 2;
    const int t2 = (lane & 3) * 2;
    if (MODE == 0) {
        __half* C = &g_PU[net][0][0];
#pragma unroll
        for (int i = 0; i < 2; i++) {
            int r0 = m0 + warp_m * 32 + i * 16 + g4;
#pragma unroll
            for (int j = 0; j < 8; j++) {
                int col = n0 + warp_n * 64 + j * 8 + t2;
                *(__half2*)&C[(size_t)r0 * NPH + col] =
                    __floats2half2_rn(acc[i][j][0], acc[i][j][1]);
                *(__half2*)&C[(size_t)(r0 + 8) * NPH + col] =
                    __floats2half2_rn(acc[i][j][2], acc[i][j][3]);
            }
        }
    } else {
        float b2v[8][2];
#pragma unroll
        for (int j = 0; j < 8; j++) {
            int col = n0 + warp_n * 64 + j * 8 + t2;
            b2v[j][0] = __ldg(&g_b2T[net][col]);
            b2v[j][1] = __ldg(&g_b2T[net][col + 1]);
        }
        const int h0i = (n0 + warp_n * 64) >> 4;
#pragma unroll
        for (int i = 0; i < 2; i++) {
#pragma unroll
            for (int hh = 0; hh < 4; hh++) {
                float mlo = -3.4e38f, mhi = -3.4e38f;
#pragma unroll
                for (int jj = 0; jj < 2; jj++) {
                    int j = hh * 2 + jj;
                    mlo = fmaxf(mlo, fmaxf(acc[i][j][0] + b2v[j][0], acc[i][j][1] + b2v[j][1]));
                    mhi = fmaxf(mhi, fmaxf(acc[i][j][2] + b2v[j][0], acc[i][j][3] + b2v[j][1]));
                }
                mlo = fmaxf(mlo, __shfl_xor_sync(0xffffffffu, mlo, 1));
                mlo = fmaxf(mlo, __shfl_xor_sync(0xffffffffu, mlo, 2));
                mhi = fmaxf(mhi, __shfl_xor_sync(0xffffffffu, mhi, 1));
                mhi = fmaxf(mhi, __shfl_xor_sync(0xffffffffu, mhi, 2));
                if ((lane & 3) == 0) {
                    int row = m0 + warp_m * 32 + i * 16 + g4;
                    g_m2[net][row][h0i + hh]     = mlo;
                    g_m2[net][row + 8][h0i + hh] = mhi;
                }
            }
        }
    }
}

// ------------------------------------------------------------------
// LSTM gates: 8 rows/block, 1 warp per row, float4 dots (own gather)
// ------------------------------------------------------------------
__global__ void lstm_gates(const float* __restrict__ U, const float* __restrict__ W_ih,
                           const float* __restrict__ W_hh, const float* __restrict__ b_ih,
                           const float* __restrict__ b_hh, int it) {
    __shared__ __align__(16) float xs[800];
    __shared__ __align__(16) float hs[HD];
    int tid = threadIdx.x;
    int s = (it == 0) ? 0 : dec_idx(g_slot[(it + 1) & 1][0]);
    int e = (it == 0) ? 0 : dec_idx(g_slot[(it + 1) & 1][1]);
    if (blockIdx.x == 0 && tid == 0) {
        g_slot[it & 1][0] = 0ull;
        g_slot[it & 1][1] = 0ull;
    }
    for (int j = tid; j < 800; j += 256)
        xs[j] = (j < 400) ? U[(size_t)j * TLEN + s] : U[(size_t)(j - 400) * TLEN + e];
    const float* hprev = g_hB[(it + 1) & 1];
    for (int j = tid; j < HD; j += 256) hs[j] = hprev[j];
    __syncthreads();
    int row = blockIdx.x * 8 + (tid >> 5);
    int lane = tid & 31;
    const float4* w4  = (const float4*)&W_ih[(size_t)row * 800];
    const float4* xs4 = (const float4*)xs;
    float acc = 0.f;
    for (int k = lane; k < 200; k += 32) acc += dot4(w4[k], xs4[k]);
    const float4* wh4 = (const float4*)&W_hh[(size_t)row * HD];
    const float4* hs4 = (const float4*)hs;
    if (lane < 25) {
        acc += dot4(wh4[lane], hs4[lane]);
        acc += dot4(wh4[lane + 25], hs4[lane + 25]);
    }
#pragma unroll
    for (int o = 16; o; o >>= 1) acc += __shfl_xor_sync(0xffffffffu, acc, o);
    if (lane == 0) g_g[row] = acc + b_ih[row] + b_hh[row];
}

// ------------------------------------------------------------------
// fused LSTM update + r = tanh(WD @ [h_new, u_s, u_e]); own gather
// ------------------------------------------------------------------
__global__ void r_kernel(const float* __restrict__ U, const float* __restrict__ WDa,
                         const float* __restrict__ WDb, int it) {
    __shared__ __align__(16) float vs[1000];
    int tid = threadIdx.x;
    int s = (it == 0) ? 0 : dec_idx(g_slot[(it + 1) & 1][0]);
    int e = (it == 0) ? 0 : dec_idx(g_slot[(it + 1) & 1][1]);
    if (tid < HD) {
        float gi = g_g[tid], gf = g_g[HD + tid], gg = g_g[2 * HD + tid], go = g_g[3 * HD + tid];
        float c = sigm(gf) * g_cB[(it + 1) & 1][tid] + sigm(gi) * tanhf(gg);
        float h = sigm(go) * tanhf(c);
        vs[tid] = h;
        if (blockIdx.x == 0) { g_cB[it & 1][tid] = c; g_hB[it & 1][tid] = h; }
    }
    for (int j = tid; j < 800; j += 256) {
        int jj = HD + j;
        vs[jj] = (j < 400) ? U[(size_t)j * TLEN + s] : U[(size_t)(j - 400) * TLEN + e];
    }
    __syncthreads();
    int row = blockIdx.x * 8 + (tid >> 5);
    int lane = tid & 31;
    int net = row / HD;
    int rr = row - net * HD;
    const float* WD = net ? WDb : WDa;
    const float4* w4  = (const float4*)&WD[(size_t)rr * 1000];
    const float4* vs4 = (const float4*)vs;
    float acc = 0.f;
    for (int k = lane; k < 250; k += 32) acc += dot4(w4[k], vs4[k]);
#pragma unroll
    for (int o = 16; o; o >>= 1) acc += __shfl_xor_sync(0xffffffffu, acc, o);
    if (lane == 0) g_r[net][rr] = tanhf(acc);
}

// ------------------------------------------------------------------
// prT[net][h*16+p] = W1r[p][h]@r + b1[p][h]; 1 output per warp, 800 blocks
// ------------------------------------------------------------------
__global__ void pr_kernel(const float* __restrict__ W1a, const float* __restrict__ W1b,
                          const float* __restrict__ b1a, const float* __restrict__ b1b) {
    int o = blockIdx.x * 8 + (threadIdx.x >> 5);
    int lane = threadIdx.x & 31;
    int net = o / NPH;
    int n = o - net * NPH;
    int h = n >> 4, p = n & 15;
    const float* W1 = net ? W1b : W1a;
    const float* b1 = net ? b1b : b1a;
    const float4* w4 = (const float4*)&W1[(size_t)(p * HD + h) * 600 + 400];
    const float4* r4 = (const float4*)g_r[net];
    float acc = 0.f;
    if (lane < 25) {
        acc += dot4(w4[lane], r4[lane]);
        acc += dot4(w4[lane + 25], r4[lane + 25]);
    }
#pragma unroll
    for (int o2 = 16; o2; o2 >>= 1) acc += __shfl_xor_sync(0xffffffffu, acc, o2);
    if (lane == 0) g_prT[net][n] = acc + b1[p * HD + h];
}

// ------------------------------------------------------------------
// m1[t][h] = max_p(PU[t][h*16+p] + prT[h*16+p]) -> single fp16
// grid (TLEN/16, 2), 256 threads; 2 items per loop step for MLP
// ------------------------------------------------------------------
__global__ void m1_kernel() {
    int net = blockIdx.y;
    int t0 = blockIdx.x * 16;
    int tid = threadIdx.x;
#pragma unroll
    for (int rep = 0; rep < 2; rep++) {
        int item0 = rep * 1600 + tid;
        // each rep covers 1600 items with 256 threads: strided sub-loop
        for (int item = item0; item < (rep + 1) * 1600; item += 256) {
            int li = item - rep * 1600;
            int tt = (rep * 1600 + li) / HD;
            int h  = (rep * 1600 + li) - tt * HD;
            if (tt >= 16) break;
            int t = t0 + tt;
            const uint4* pu4 = (const uint4*)&g_PU[net][t][h << 4];
            const float4* pr = (const float4*)&g_prT[net][h << 4];
            uint4 v0 = pu4[0], v1 = pu4[1];
            const __half2* a = (const __half2*)&v0;
            const __half2* b = (const __half2*)&v1;
            float m = -3.4e38f;
#pragma unroll
            for (int q = 0; q < 2; q++) {
                float4 pv = pr[q];
                float2 a0 = __half22float2(a[q * 2]);
                float2 a1 = __half22float2(a[q * 2 + 1]);
                m = fmaxf(m, fmaxf(fmaxf(a0.x + pv.x, a0.y + pv.y), fmaxf(a1.x + pv.z, a1.y + pv.w)));
            }
#pragma unroll
            for (int q = 0; q < 2; q++) {
                float4 pv = pr[2 + q];
                float2 a0 = __half22float2(b[q * 2]);
                float2 a1 = __half22float2(b[q * 2 + 1]);
                m = fmaxf(m, fmaxf(fmaxf(a0.x + pv.x, a0.y + pv.y), fmaxf(a1.x + pv.z, a1.y + pv.w)));
            }
            g_m1[net][t][h] = __float2half(m);
        }
    }
}

// ------------------------------------------------------------------
// scores + fused argmax: 64 t per block, 512 threads
// ------------------------------------------------------------------
#define SCORE_SMEM ((64 * 408 + 16 * 401 + 128) * 4)
__global__ void __launch_bounds__(512) score_kernel(
        const float* __restrict__ W3a, const float* __restrict__ W3b,
        const float* __restrict__ b3a, const float* __restrict__ b3b,
        float* __restrict__ out, int it, int maxI) {
    extern __shared__ float sm[];
    float* ms  = sm;                 // [64][408]
    float* w3s = sm + 64 * 408;      // [16][401]
    float* bmx = w3s + 16 * 401;     // [64]
    int*   bmi = (int*)(bmx + 64);   // [64]
    int net = blockIdx.y;
    int t0 = blockIdx.x * 64;
    int tid = threadIdx.x;
    const float* W3 = net ? W3b : W3a;
    for (int idx = tid; idx < 6400; idx += 512) {
        int p = idx / 400, d = idx - p * 400;
        w3s[p * 401 + d] = W3[p * 400 + d];
    }
    for (int idx = tid; idx < 64 * HD; idx += 512) {
        int tt = idx / HD, h = idx - tt * HD;
        int t = t0 + tt;
        ms[tt * 408 + h] = __half2float(g_m1[net][t][h]);
        ms[tt * 408 + 200 + h] = g_m2[net][t][h];
    }
    __syncthreads();
    int grp = tid >> 4, p = tid & 15;
    float bias = (net ? b3b : b3a)[p];
    const float* w3r = &w3s[p * 401];
#pragma unroll
    for (int rep = 0; rep < 2; rep++) {
        int tt = grp + rep * 32;
        float acc = bias;
        const float* msr = &ms[tt * 408];
#pragma unroll 4
        for (int d = 0; d < 400; d++) acc = fmaf(msr[d], w3r[d], acc);
#pragma unroll
        for (int o = 8; o; o >>= 1) acc = fmaxf(acc, __shfl_xor_sync(0xffffffffu, acc, o));
        if (p == 0) {
            out[((size_t)net * maxI + it) * TLEN + t0 + tt] = acc;
            bmx[tt] = acc;
            bmi[tt] = t0 + tt;
        }
    }
    __syncthreads();
    if (tid == 0) {
        float bv = bmx[0]; int bi = bmi[0];
        for (int q = 1; q < 64; q++) {
            if (bmx[q] > bv) { bv = bmx[q]; bi = bmi[q]; }
        }
        atomicMax(&g_slot[it & 1][net], enc_max(bv, bi));
    }
}

__global__ void finalize_kernel(float* __restrict__ out, int maxI) {
    out[(size_t)2 * maxI * TLEN + 0] = (float)dec_idx(g_slot[(maxI - 1) & 1][0]);
    out[(size_t)2 * maxI * TLEN + 1] = (float)dec_idx(g_slot[(maxI - 1) & 1][1]);
}

// ------------------------------------------------------------------
// launch
// ------------------------------------------------------------------
extern "C" void kernel_launch(void* const* d_in, const int* in_sizes, int n_in,
                              void* d_out, int out_size) {
    const float* U    = (const float*)d_in[0];
    const float* h0   = (const float*)d_in[2];
    const float* c0   = (const float*)d_in[3];
    const float* W_ih = (const float*)d_in[4];
    const float* W_hh = (const float*)d_in[5];
    const float* b_ih = (const float*)d_in[6];
    const float* b_hh = (const float*)d_in[7];
    const float* WD_a = (const float*)d_in[8];
    const float* W1_a = (const float*)d_in[9];
    const float* b1_a = (const float*)d_in[10];
    const float* W2_a = (const float*)d_in[11];
    const float* b2_a = (const float*)d_in[12];
    const float* W3_a = (const float*)d_in[13];
    const float* b3_a = (const float*)d_in[14];
    const float* WD_b = (const float*)d_in[15];
    const float* W1_b = (const float*)d_in[16];
    const float* b1_b = (const float*)d_in[17];
    const float* W2_b = (const float*)d_in[18];
    const float* b2_b = (const float*)d_in[19];
    const float* W3_b = (const float*)d_in[20];
    const float* b3_b = (const float*)d_in[21];
    float* out = (float*)d_out;

    int maxI = out_size / (2 * TLEN);
    if (maxI < 1) maxI = 1;
    int write_se = (out_size >= 2 * maxI * TLEN + 2) ? 1 : 0;

    cudaFuncSetAttribute(gemm_mma<0>, cudaFuncAttributeMaxDynamicSharedMemorySize, GEMM_SMEM);
    cudaFuncSetAttribute(gemm_mma<1>, cudaFuncAttributeMaxDynamicSharedMemorySize, GEMM_SMEM);
    cudaFuncSetAttribute(score_kernel, cudaFuncAttributeMaxDynamicSharedMemorySize, SCORE_SMEM);

    prep_UT<<<dim3(K1PAD / 32, TLEN / 32), dim3(32, 8)>>>(U);
    prep_B1<<<dim3(K1PAD / 32, NPH / 32, 2), dim3(32, 8)>>>(W1_a, W1_b);
    prep_B2<<<dim3(K2PAD / 32, NPH / 32, 2), dim3(32, 8)>>>(W2_a, W2_b);
    prep_misc<<<128, 256>>>(b2_a, b2_b, h0, c0);
    gemm_mma<0><<<dim3(TLEN / 128, NPH / 128, 2), 256, GEMM_SMEM>>>();

    for (int it = 0; it < maxI; it++) {
        lstm_gates<<<100, 256>>>(U, W_ih, W_hh, b_ih, b_hh, it);
        r_kernel<<<50, 256>>>(U, WD_a, WD_b, it);
        pr_kernel<<<800, 256>>>(W1_a, W1_b, b1_a, b1_b);
        m1_kernel<<<dim3(TLEN / 16, 2), 256>>>();
        gemm_mma<1><<<dim3(TLEN / 128, NPH / 128, 2), 256, GEMM_SMEM>>>();
        score_kernel<<<dim3(TLEN / 64, 2), 512, SCORE_SMEM>>>(W3_a, W3_b, b3_a, b3_b, out, it, maxI);
    }
    if (write_se) finalize_kernel<<<1, 1>>>(out, maxI);
}

// round 14
// speedup vs baseline: 1.1277x; 1.0497x over previous
#include <cuda_runtime.h>
#include <cuda_fp16.h>
#include <math.h>
#include <stdint.h>

#define HD    200
#define POOL  16
#define TLEN  4096
#define NPH   3200   // POOL*HD
#define K1PAD 416    // pad of 2*HD=400 to mult of 32
#define K2PAD 224    // pad of HD=200 to mult of 32

// ------------------------------------------------------------------
// Static device scratch
// ------------------------------------------------------------------
__device__ __align__(16) __half g_UT[TLEN][K1PAD];        // A1 [t][k]
__device__ __align__(16) __half g_B1[2][K1PAD][NPH];      // B1 [k][n]
__device__ __align__(16) __half g_B2[2][K2PAD][NPH];      // B2 [k][n]
__device__ __align__(16) __half g_m1[2][TLEN][K2PAD];     // A2 [t][k]
__device__ __align__(16) __half g_PU[2][TLEN][NPH];       // fp16, 52 MB
__device__ __align__(16) float g_m2[2][TLEN][HD];
__device__ __align__(16) float g_b2T[2][NPH];
__device__ __align__(16) float g_prT[2][NPH];
__device__ __align__(16) float g_x[800];                  // mirrored [u_s, u_e]
__device__ float g_g[4 * HD];
__device__ float g_hB[2][HD];
__device__ float g_cB[2][HD];
__device__ float g_r[2][HD];
__device__ unsigned long long g_slot[2][2];

// ------------------------------------------------------------------
// helpers
// ------------------------------------------------------------------
__device__ __forceinline__ uint32_t smem_u32(const void* p) {
    uint32_t a;
    asm("{ .reg .u64 t; cvta.to.shared.u64 t, %1; cvt.u32.u64 %0, t; }" : "=r"(a) : "l"(p));
    return a;
}
__device__ __forceinline__ void cp16(uint32_t dst, const void* src) {
    asm volatile("cp.async.cg.shared.global [%0], [%1], 16;" :: "r"(dst), "l"(src));
}
#define CP_COMMIT() asm volatile("cp.async.commit_group;" ::: "memory")
#define CP_WAIT1()  asm volatile("cp.async.wait_group 1;" ::: "memory")

__device__ __forceinline__ void ldsm4(uint32_t* r, uint32_t addr) {
    asm volatile("ldmatrix.sync.aligned.m8n8.x4.shared.b16 {%0,%1,%2,%3}, [%4];"
                 : "=r"(r[0]), "=r"(r[1]), "=r"(r[2]), "=r"(r[3]) : "r"(addr));
}
__device__ __forceinline__ void ldsm4t(uint32_t* r, uint32_t addr) {
    asm volatile("ldmatrix.sync.aligned.m8n8.x4.trans.shared.b16 {%0,%1,%2,%3}, [%4];"
                 : "=r"(r[0]), "=r"(r[1]), "=r"(r[2]), "=r"(r[3]) : "r"(addr));
}
__device__ __forceinline__ void mma_f16(float* c, const uint32_t* a, const uint32_t* b) {
    asm volatile(
        "mma.sync.aligned.m16n8k16.row.col.f32.f16.f16.f32 "
        "{%0,%1,%2,%3}, {%4,%5,%6,%7}, {%8,%9}, {%0,%1,%2,%3};"
        : "+f"(c[0]), "+f"(c[1]), "+f"(c[2]), "+f"(c[3])
        : "r"(a[0]), "r"(a[1]), "r"(a[2]), "r"(a[3]), "r"(b[0]), "r"(b[1]));
}
__device__ __forceinline__ float sigm(float x) { return 1.0f / (1.0f + expf(-x)); }
__device__ __forceinline__ unsigned long long enc_max(float v, int t) {
    uint32_t u = __float_as_uint(v);
    u = (u & 0x80000000u) ? ~u : (u | 0x80000000u);
    return ((unsigned long long)u << 32) | (uint32_t)(TLEN - 1 - t);
}
__device__ __forceinline__ int dec_idx(unsigned long long s) {
    return TLEN - 1 - (int)(uint32_t)(s & 0xFFFFFFFFull);
}
__device__ __forceinline__ float dot4(float4 a, float4 b) {
    return a.x * b.x + a.y * b.y + a.z * b.z + a.w * b.w;
}

// ------------------------------------------------------------------
// prep: tiled transposes (all global accesses coalesced)
// ------------------------------------------------------------------
__global__ void prep_UT(const float* __restrict__ U) {
    __shared__ float tile[32][33];
    int k0 = blockIdx.x * 32, t0 = blockIdx.y * 32;
    int tx = threadIdx.x, ty0 = threadIdx.y;
#pragma unroll
    for (int i = 0; i < 4; i++) {
        int tk = ty0 * 4 + i;
        int k = k0 + tk;
        tile[tk][tx] = (k < 2 * HD) ? U[(size_t)k * TLEN + t0 + tx] : 0.f;
    }
    __syncthreads();
#pragma unroll
    for (int i = 0; i < 4; i++) {
        int tt = ty0 * 4 + i;
        g_UT[t0 + tt][k0 + tx] = __float2half(tile[tx][tt]);
    }
}

__global__ void prep_B1(const float* __restrict__ W1a, const float* __restrict__ W1b) {
    __shared__ float tile[32][33];
    int net = blockIdx.z;
    int k0 = blockIdx.x * 32, n0 = blockIdx.y * 32;
    int tx = threadIdx.x, ty0 = threadIdx.y;
    const float* W1 = net ? W1b : W1a;
#pragma unroll
    for (int i = 0; i < 4; i++) {
        int ty = ty0 * 4 + i;
        int n = n0 + ty;
        int h = n >> 4, p = n & 15;
        int k = k0 + tx;
        tile[ty][tx] = (k < 2 * HD) ? W1[(size_t)(p * HD + h) * 600 + k] : 0.f;
    }
    __syncthreads();
#pragma unroll
    for (int i = 0; i < 4; i++) {
        int ty = ty0 * 4 + i;
        g_B1[net][k0 + ty][n0 + tx] = __float2half(tile[tx][ty]);
    }
}

__global__ void prep_B2(const float* __restrict__ W2a, const float* __restrict__ W2b) {
    __shared__ float tile[32][33];
    int net = blockIdx.z;
    int k0 = blockIdx.x * 32, n0 = blockIdx.y * 32;
    int tx = threadIdx.x, ty0 = threadIdx.y;
    const float* W2 = net ? W2b : W2a;
#pragma unroll
    for (int i = 0; i < 4; i++) {
        int ty = ty0 * 4 + i;
        int n = n0 + ty;
        int h = n >> 4, p = n & 15;
        int k = k0 + tx;
        tile[ty][tx] = (k < HD) ? W2[(size_t)(p * HD + h) * HD + k] : 0.f;
    }
    __syncthreads();
#pragma unroll
    for (int i = 0; i < 4; i++) {
        int ty = ty0 * 4 + i;
        g_B2[net][k0 + ty][n0 + tx] = __float2half(tile[tx][ty]);
    }
}

__global__ void prep_misc(const float* __restrict__ b2a, const float* __restrict__ b2b,
                          const float* __restrict__ h0,  const float* __restrict__ c0) {
    int idx0 = blockIdx.x * blockDim.x + threadIdx.x;
    int stride = gridDim.x * blockDim.x;
    for (int i = idx0; i < 2 * NPH; i += stride) {
        int net = i / NPH, n = i - net * NPH;
        int h = n >> 4, p = n & 15;
        const float* b2 = net ? b2b : b2a;
        g_b2T[net][n] = b2[p * HD + h];
    }
    for (int i = idx0; i < 2 * TLEN * (K2PAD - HD); i += stride) {
        int net = i / (TLEN * (K2PAD - HD));
        int rem = i - net * (TLEN * (K2PAD - HD));
        int t = rem / (K2PAD - HD);
        int k = HD + (rem - t * (K2PAD - HD));
        g_m1[net][t][k] = __float2half(0.f);
    }
    if (idx0 < HD) { g_hB[1][idx0] = h0[idx0]; g_cB[1][idx0] = c0[idx0]; }
}

// ------------------------------------------------------------------
// mma.sync GEMM (round-10 proven shape): C[t][n] = sum_k A[t][k]*B[k][n]
// MODE 0: A=UT (K=416), B=B1 -> fp16 store to g_PU
// MODE 1: A=m1 (K=224), B=B2 -> +b2T, max over p -> g_m2[t][h]
// Block tile 128x128, 256 threads, 8 warps (4m x 2n), warp 32x64,
// K-chunk 32, 3-stage cp.async pipeline (wait_group 1). 2 CTAs/SM.
// ------------------------------------------------------------------
#define A_ROW_B   80
#define A_STG_B   10240
#define B_ROW_B   272
#define B_STG_B   8704
#define OFF_B     30720              // 3 * A_STG_B
#define GEMM_SMEM (30720 + 26112)    // 3 A stages + 3 B stages = 56832

template <int MODE>
__global__ void __launch_bounds__(256) gemm_mma() {
    extern __shared__ char smem[];
    const int tid    = threadIdx.x;
    const int lane   = tid & 31;
    const int wid    = tid >> 5;
    const int warp_m = wid & 3;
    const int warp_n = wid >> 2;
    const int net    = blockIdx.z;
    const int m0     = blockIdx.x * 128;
    const int n0     = blockIdx.y * 128;
    const int KPAD   = (MODE == 0) ? K1PAD : K2PAD;
    const int NC     = KPAD / 32;

    const __half* __restrict__ Ap = (MODE == 0) ? &g_UT[0][0] : &g_m1[net][0][0];
    const __half* __restrict__ Bp = (MODE == 0) ? &g_B1[net][0][0] : &g_B2[net][0][0];

    const uint32_t sb = smem_u32(smem);

    const int arow = tid >> 1;
    const int aq   = (tid & 1) * 2;
    const int brow = tid >> 3;
    const int bq   = tid & 7;

    auto load_stage = [&](int stage, int kc) {
        const uint32_t as = sb + stage * A_STG_B + arow * A_ROW_B + aq * 16;
        const __half* ah = Ap + (size_t)(m0 + arow) * KPAD + kc + aq * 8;
        cp16(as,      ah);
        cp16(as + 16, ah + 8);
        const uint32_t bs = sb + OFF_B + stage * B_STG_B + brow * B_ROW_B + bq * 32;
        const __half* bg = Bp + (size_t)(kc + brow) * NPH + n0 + bq * 16;
        cp16(bs,      bg);
        cp16(bs + 16, bg + 8);
    };

    float acc[2][8][4];
#pragma unroll
    for (int i = 0; i < 2; i++)
#pragma unroll
        for (int j = 0; j < 8; j++)
#pragma unroll
            for (int q = 0; q < 4; q++) acc[i][j][q] = 0.f;

    const int l15 = lane & 15;
    const int l16 = (lane >> 4) * 8;
    const uint32_t aBase = sb + (warp_m * 32 + l15) * A_ROW_B + l16 * 2;
    const uint32_t bBase = sb + OFF_B + l15 * B_ROW_B + (warp_n * 64 + l16) * 2;

    load_stage(0, 0);
    CP_COMMIT();
    load_stage(1, 32);
    CP_COMMIT();

    for (int c = 0; c < NC; c++) {
        CP_WAIT1();
        __syncthreads();
        const int stg = c % 3;
        const uint32_t aS = aBase + stg * A_STG_B;
        const uint32_t bS = bBase + stg * B_STG_B;
#pragma unroll
        for (int s = 0; s < 2; s++) {
            uint32_t ah[2][4];
#pragma unroll
            for (int i = 0; i < 2; i++)
                ldsm4(ah[i], aS + i * 16 * A_ROW_B + s * 32);
#pragma unroll
            for (int half = 0; half < 2; half++) {
                uint32_t bb[4][2];
#pragma unroll
                for (int pr = 0; pr < 2; pr++) {
                    uint32_t r[4];
                    ldsm4t(r, bS + s * 16 * B_ROW_B + (half * 2 + pr) * 32);
                    bb[pr * 2][0] = r[0]; bb[pr * 2][1] = r[1];
                    bb[pr * 2 + 1][0] = r[2]; bb[pr * 2 + 1][1] = r[3];
                }
#pragma unroll
                for (int i = 0; i < 2; i++)
#pragma unroll
                    for (int j = 0; j < 4; j++)
                        mma_f16(acc[i][half * 4 + j], ah[i], bb[j]);
            }
        }
        if (c + 2 < NC) { load_stage((c + 2) % 3, (c + 2) * 32); }
        CP_COMMIT();
    }

    const int g4 = lane >> 2;
    const int t2 = (lane & 3) * 2;
    if (MODE == 0) {
        __half* C = &g_PU[net][0][0];
#pragma unroll
        for (int i = 0; i < 2; i++) {
            int r0 = m0 + warp_m * 32 + i * 16 + g4;
#pragma unroll
            for (int j = 0; j < 8; j++) {
                int col = n0 + warp_n * 64 + j * 8 + t2;
                *(__half2*)&C[(size_t)r0 * NPH + col] =
                    __floats2half2_rn(acc[i][j][0], acc[i][j][1]);
                *(__half2*)&C[(size_t)(r0 + 8) * NPH + col] =
                    __floats2half2_rn(acc[i][j][2], acc[i][j][3]);
            }
        }
    } else {
        float b2v[8][2];
#pragma unroll
        for (int j = 0; j < 8; j++) {
            int col = n0 + warp_n * 64 + j * 8 + t2;
            b2v[j][0] = __ldg(&g_b2T[net][col]);
            b2v[j][1] = __ldg(&g_b2T[net][col + 1]);
        }
        const int h0i = (n0 + warp_n * 64) >> 4;
#pragma unroll
        for (int i = 0; i < 2; i++) {
#pragma unroll
            for (int hh = 0; hh < 4; hh++) {
                float mlo = -3.4e38f, mhi = -3.4e38f;
#pragma unroll
                for (int jj = 0; jj < 2; jj++) {
                    int j = hh * 2 + jj;
                    mlo = fmaxf(mlo, fmaxf(acc[i][j][0] + b2v[j][0], acc[i][j][1] + b2v[j][1]));
                    mhi = fmaxf(mhi, fmaxf(acc[i][j][2] + b2v[j][0], acc[i][j][3] + b2v[j][1]));
                }
                mlo = fmaxf(mlo, __shfl_xor_sync(0xffffffffu, mlo, 1));
                mlo = fmaxf(mlo, __shfl_xor_sync(0xffffffffu, mlo, 2));
                mhi = fmaxf(mhi, __shfl_xor_sync(0xffffffffu, mhi, 1));
                mhi = fmaxf(mhi, __shfl_xor_sync(0xffffffffu, mhi, 2));
                if ((lane & 3) == 0) {
                    int row = m0 + warp_m * 32 + i * 16 + g4;
                    g_m2[net][row][h0i + hh]     = mlo;
                    g_m2[net][row + 8][h0i + hh] = mhi;
                }
            }
        }
    }
}

// ------------------------------------------------------------------
// LSTM gates: 8 rows/block, 1 warp per row; block 0 mirrors xs -> g_x
// ------------------------------------------------------------------
__global__ void lstm_gates(const float* __restrict__ U, const float* __restrict__ W_ih,
                           const float* __restrict__ W_hh, const float* __restrict__ b_ih,
                           const float* __restrict__ b_hh, int it) {
    __shared__ __align__(16) float xs[800];
    __shared__ __align__(16) float hs[HD];
    int tid = threadIdx.x;
    int s = (it == 0) ? 0 : dec_idx(g_slot[(it + 1) & 1][0]);
    int e = (it == 0) ? 0 : dec_idx(g_slot[(it + 1) & 1][1]);
    if (blockIdx.x == 0 && tid == 0) {
        g_slot[it & 1][0] = 0ull;
        g_slot[it & 1][1] = 0ull;
    }
    for (int j = tid; j < 800; j += 256) {
        float v = (j < 400) ? U[(size_t)j * TLEN + s] : U[(size_t)(j - 400) * TLEN + e];
        xs[j] = v;
        if (blockIdx.x == 0) g_x[j] = v;
    }
    const float* hprev = g_hB[(it + 1) & 1];
    for (int j = tid; j < HD; j += 256) hs[j] = hprev[j];
    __syncthreads();
    int row = blockIdx.x * 8 + (tid >> 5);
    int lane = tid & 31;
    const float4* w4  = (const float4*)&W_ih[(size_t)row * 800];
    const float4* xs4 = (const float4*)xs;
    float acc = 0.f;
    for (int k = lane; k < 200; k += 32) acc += dot4(w4[k], xs4[k]);
    const float4* wh4 = (const float4*)&W_hh[(size_t)row * HD];
    const float4* hs4 = (const float4*)hs;
    if (lane < 25) {
        acc += dot4(wh4[lane], hs4[lane]);
        acc += dot4(wh4[lane + 25], hs4[lane + 25]);
    }
#pragma unroll
    for (int o = 16; o; o >>= 1) acc += __shfl_xor_sync(0xffffffffu, acc, o);
    if (lane == 0) g_g[row] = acc + b_ih[row] + b_hh[row];
}

// ------------------------------------------------------------------
// fused LSTM update + r = tanh(WD @ [h_new, u_s, u_e]); x from g_x
// ------------------------------------------------------------------
__global__ void r_kernel(const float* __restrict__ WDa, const float* __restrict__ WDb,
                         int it) {
    __shared__ __align__(16) float vs[1000];
    int tid = threadIdx.x;
    if (tid < HD) {
        float gi = g_g[tid], gf = g_g[HD + tid], gg = g_g[2 * HD + tid], go = g_g[3 * HD + tid];
        float c = sigm(gf) * g_cB[(it + 1) & 1][tid] + sigm(gi) * tanhf(gg);
        float h = sigm(go) * tanhf(c);
        vs[tid] = h;
        if (blockIdx.x == 0) { g_cB[it & 1][tid] = c; g_hB[it & 1][tid] = h; }
    }
    for (int j = tid; j < 800; j += 256) vs[HD + j] = g_x[j];
    __syncthreads();
    int row = blockIdx.x * 8 + (tid >> 5);
    int lane = tid & 31;
    int net = row / HD;
    int rr = row - net * HD;
    const float* WD = net ? WDb : WDa;
    const float4* w4  = (const float4*)&WD[(size_t)rr * 1000];
    const float4* vs4 = (const float4*)vs;
    float acc = 0.f;
    for (int k = lane; k < 250; k += 32) acc += dot4(w4[k], vs4[k]);
#pragma unroll
    for (int o = 16; o; o >>= 1) acc += __shfl_xor_sync(0xffffffffu, acc, o);
    if (lane == 0) g_r[net][rr] = tanhf(acc);
}

// ------------------------------------------------------------------
// prT[net][h*16+p] = W1r[p][h]@r + b1[p][h]; 1 output/warp, 800 blocks
// ------------------------------------------------------------------
__global__ void pr_kernel(const float* __restrict__ W1a, const float* __restrict__ W1b,
                          const float* __restrict__ b1a, const float* __restrict__ b1b) {
    int o = blockIdx.x * 8 + (threadIdx.x >> 5);
    int lane = threadIdx.x & 31;
    int net = o / NPH;
    int n = o - net * NPH;
    int h = n >> 4, p = n & 15;
    const float* W1 = net ? W1b : W1a;
    const float* b1 = net ? b1b : b1a;
    const float4* w4 = (const float4*)&W1[(size_t)(p * HD + h) * 600 + 400];
    const float4* r4 = (const float4*)g_r[net];
    float acc = 0.f;
    if (lane < 25) {
        acc += dot4(w4[lane], r4[lane]);
        acc += dot4(w4[lane + 25], r4[lane + 25]);
    }
#pragma unroll
    for (int o2 = 16; o2; o2 >>= 1) acc += __shfl_xor_sync(0xffffffffu, acc, o2);
    if (lane == 0) g_prT[net][n] = acc + b1[p * HD + h];
}

// ------------------------------------------------------------------
// m1[t][h] = max_p(PU[t][h*16+p] + prT[h*16+p]) -> single fp16
// grid (TLEN/16, 2), 256 threads; 16B vector loads of PU
// ------------------------------------------------------------------
__global__ void m1_kernel() {
    int net = blockIdx.y;
    int t0 = blockIdx.x * 16;
    int tid = threadIdx.x;
    for (int item = tid; item < 16 * HD; item += 256) {
        int tt = item / HD, h = item - tt * HD;
        int t = t0 + tt;
        const uint4* pu4 = (const uint4*)&g_PU[net][t][h << 4];
        const float4* pr = (const float4*)&g_prT[net][h << 4];
        uint4 v0 = pu4[0], v1 = pu4[1];
        const __half2* a = (const __half2*)&v0;
        const __half2* b = (const __half2*)&v1;
        float m = -3.4e38f;
#pragma unroll
        for (int q = 0; q < 2; q++) {
            float4 pv = pr[q];
            float2 a0 = __half22float2(a[q * 2]);
            float2 a1 = __half22float2(a[q * 2 + 1]);
            m = fmaxf(m, fmaxf(fmaxf(a0.x + pv.x, a0.y + pv.y), fmaxf(a1.x + pv.z, a1.y + pv.w)));
        }
#pragma unroll
        for (int q = 0; q < 2; q++) {
            float4 pv = pr[2 + q];
            float2 a0 = __half22float2(b[q * 2]);
            float2 a1 = __half22float2(b[q * 2 + 1]);
            m = fmaxf(m, fmaxf(fmaxf(a0.x + pv.x, a0.y + pv.y), fmaxf(a1.x + pv.z, a1.y + pv.w)));
        }
        g_m1[net][t][h] = __float2half(m);
    }
}

// ------------------------------------------------------------------
// scores + fused argmax: 64 t per block, 512 threads
// ------------------------------------------------------------------
#define SCORE_SMEM ((64 * 408 + 16 * 401 + 128) * 4)
__global__ void __launch_bounds__(512) score_kernel(
        const float* __restrict__ W3a, const float* __restrict__ W3b,
        const float* __restrict__ b3a, const float* __restrict__ b3b,
        float* __restrict__ out, int it, int maxI) {
    extern __shared__ float sm[];
    float* ms  = sm;                 // [64][408]
    float* w3s = sm + 64 * 408;      // [16][401]
    float* bmx = w3s + 16 * 401;     // [64]
    int*   bmi = (int*)(bmx + 64);   // [64]
    int net = blockIdx.y;
    int t0 = blockIdx.x * 64;
    int tid = threadIdx.x;
    const float* W3 = net ? W3b : W3a;
    for (int idx = tid; idx < 6400; idx += 512) {
        int p = idx / 400, d = idx - p * 400;
        w3s[p * 401 + d] = W3[p * 400 + d];
    }
    for (int idx = tid; idx < 64 * HD; idx += 512) {
        int tt = idx / HD, h = idx - tt * HD;
        int t = t0 + tt;
        ms[tt * 408 + h] = __half2float(g_m1[net][t][h]);
        ms[tt * 408 + 200 + h] = g_m2[net][t][h];
    }
    __syncthreads();
    int grp = tid >> 4, p = tid & 15;
    float bias = (net ? b3b : b3a)[p];
    const float* w3r = &w3s[p * 401];
#pragma unroll
    for (int rep = 0; rep < 2; rep++) {
        int tt = grp + rep * 32;
        float acc = bias;
        const float* msr = &ms[tt * 408];
#pragma unroll 4
        for (int d = 0; d < 400; d++) acc = fmaf(msr[d], w3r[d], acc);
#pragma unroll
        for (int o = 8; o; o >>= 1) acc = fmaxf(acc, __shfl_xor_sync(0xffffffffu, acc, o));
        if (p == 0) {
            out[((size_t)net * maxI + it) * TLEN + t0 + tt] = acc;
            bmx[tt] = acc;
            bmi[tt] = t0 + tt;
        }
    }
    __syncthreads();
    if (tid == 0) {
        float bv = bmx[0]; int bi = bmi[0];
        for (int q = 1; q < 64; q++) {
            if (bmx[q] > bv) { bv = bmx[q]; bi = bmi[q]; }
        }
        atomicMax(&g_slot[it & 1][net], enc_max(bv, bi));
    }
}

__global__ void finalize_kernel(float* __restrict__ out, int maxI) {
    out[(size_t)2 * maxI * TLEN + 0] = (float)dec_idx(g_slot[(maxI - 1) & 1][0]);
    out[(size_t)2 * maxI * TLEN + 1] = (float)dec_idx(g_slot[(maxI - 1) & 1][1]);
}

// ------------------------------------------------------------------
// launch: fork gemm0 path onto a side stream (graph-capture fork/join)
// ------------------------------------------------------------------
extern "C" void kernel_launch(void* const* d_in, const int* in_sizes, int n_in,
                              void* d_out, int out_size) {
    const float* U    = (const float*)d_in[0];
    const float* h0   = (const float*)d_in[2];
    const float* c0   = (const float*)d_in[3];
    const float* W_ih = (const float*)d_in[4];
    const float* W_hh = (const float*)d_in[5];
    const float* b_ih = (const float*)d_in[6];
    const float* b_hh = (const float*)d_in[7];
    const float* WD_a = (const float*)d_in[8];
    const float* W1_a = (const float*)d_in[9];
    const float* b1_a = (const float*)d_in[10];
    const float* W2_a = (const float*)d_in[11];
    const float* b2_a = (const float*)d_in[12];
    const float* W3_a = (const float*)d_in[13];
    const float* b3_a = (const float*)d_in[14];
    const float* WD_b = (const float*)d_in[15];
    const float* W1_b = (const float*)d_in[16];
    const float* b1_b = (const float*)d_in[17];
    const float* W2_b = (const float*)d_in[18];
    const float* b2_b = (const float*)d_in[19];
    const float* W3_b = (const float*)d_in[20];
    const float* b3_b = (const float*)d_in[21];
    float* out = (float*)d_out;

    int maxI = out_size / (2 * TLEN);
    if (maxI < 1) maxI = 1;
    int write_se = (out_size >= 2 * maxI * TLEN + 2) ? 1 : 0;

    cudaFuncSetAttribute(gemm_mma<0>, cudaFuncAttributeMaxDynamicSharedMemorySize, GEMM_SMEM);
    cudaFuncSetAttribute(gemm_mma<1>, cudaFuncAttributeMaxDynamicSharedMemorySize, GEMM_SMEM);
    cudaFuncSetAttribute(score_kernel, cudaFuncAttributeMaxDynamicSharedMemorySize, SCORE_SMEM);

    cudaStream_t s1;
    cudaStreamCreateWithFlags(&s1, cudaStreamNonBlocking);
    cudaEvent_t evFork, evG0;
    cudaEventCreateWithFlags(&evFork, cudaEventDisableTiming);
    cudaEventCreateWithFlags(&evG0, cudaEventDisableTiming);

    // fork: side stream builds UT+B1 then runs gemm0 (PU)
    cudaEventRecord(evFork, 0);
    cudaStreamWaitEvent(s1, evFork, 0);
    prep_UT<<<dim3(K1PAD / 32, TLEN / 32), dim3(32, 8), 0, s1>>>(U);
    prep_B1<<<dim3(K1PAD / 32, NPH / 32, 2), dim3(32, 8), 0, s1>>>(W1_a, W1_b);
    gemm_mma<0><<<dim3(TLEN / 128, NPH / 128, 2), 256, GEMM_SMEM, s1>>>();
    cudaEventRecord(evG0, s1);

    // main stream: independent prep + iter-0 scalar chain
    prep_B2<<<dim3(K2PAD / 32, NPH / 32, 2), dim3(32, 8)>>>(W2_a, W2_b);
    prep_misc<<<128, 256>>>(b2_a, b2_b, h0, c0);

    for (int it = 0; it < maxI; it++) {
        lstm_gates<<<100, 256>>>(U, W_ih, W_hh, b_ih, b_hh, it);
        r_kernel<<<50, 256>>>(WD_a, WD_b, it);
        pr_kernel<<<800, 256>>>(W1_a, W1_b, b1_a, b1_b);
        if (it == 0) cudaStreamWaitEvent(0, evG0, 0);   // join: m1 needs PU
        m1_kernel<<<dim3(TLEN / 16, 2), 256>>>();
        gemm_mma<1><<<dim3(TLEN / 128, NPH / 128, 2), 256, GEMM_SMEM>>>();
        score_kernel<<<dim3(TLEN / 64, 2), 512, SCORE_SMEM>>>(W3_a, W3_b, b3_a, b3_b, out, it, maxI);
    }
    if (write_se) finalize_kernel<<<1, 1>>>(out, maxI);

    cudaEventDestroy(evFork);
    cudaEventDestroy(evG0);
    cudaStreamDestroy(s1);
}

// round 15
// speedup vs baseline: 1.1330x; 1.0047x over previous
#include <cuda_runtime.h>
#include <cuda_fp16.h>
#include <math.h>
#include <stdint.h>

#define HD    200
#define POOL  16
#define TLEN  4096
#define NPH   3200   // POOL*HD
#define K1PAD 416    // pad of 2*HD=400 to mult of 32
#define K2PAD 224    // pad of HD=200 to mult of 32

// ------------------------------------------------------------------
// Static device scratch
// ------------------------------------------------------------------
__device__ __align__(16) __half g_UT[TLEN][K1PAD];        // A1 [t][k]
__device__ __align__(16) __half g_B1[2][K1PAD][NPH];      // B1 [k][n]
__device__ __align__(16) __half g_B2[2][K2PAD][NPH];      // B2 [k][n]
__device__ __align__(16) __half g_m1[2][TLEN][K2PAD];     // A2 [t][k]
__device__ __align__(16) __half g_PU[2][TLEN][NPH];       // fp16, 52 MB
__device__ __align__(16) float g_m2[2][TLEN][HD];
__device__ __align__(16) float g_b2T[2][NPH];
__device__ __align__(16) float g_prT[2][NPH];
__device__ __align__(16) float g_x[800];                  // mirrored [u_s, u_e]
__device__ float g_g[4 * HD];
__device__ float g_hB[2][HD];
__device__ float g_cB[2][HD];
__device__ float g_r[2][HD];
__device__ unsigned long long g_slot[2][2];

// ------------------------------------------------------------------
// helpers
// ------------------------------------------------------------------
__device__ __forceinline__ uint32_t smem_u32(const void* p) {
    uint32_t a;
    asm("{ .reg .u64 t; cvta.to.shared.u64 t, %1; cvt.u32.u64 %0, t; }" : "=r"(a) : "l"(p));
    return a;
}
__device__ __forceinline__ void cp16(uint32_t dst, const void* src) {
    asm volatile("cp.async.cg.shared.global [%0], [%1], 16;" :: "r"(dst), "l"(src));
}
#define CP_COMMIT() asm volatile("cp.async.commit_group;" ::: "memory")
#define CP_WAIT1()  asm volatile("cp.async.wait_group 1;" ::: "memory")

__device__ __forceinline__ void ldsm4(uint32_t* r, uint32_t addr) {
    asm volatile("ldmatrix.sync.aligned.m8n8.x4.shared.b16 {%0,%1,%2,%3}, [%4];"
                 : "=r"(r[0]), "=r"(r[1]), "=r"(r[2]), "=r"(r[3]) : "r"(addr));
}
__device__ __forceinline__ void ldsm4t(uint32_t* r, uint32_t addr) {
    asm volatile("ldmatrix.sync.aligned.m8n8.x4.trans.shared.b16 {%0,%1,%2,%3}, [%4];"
                 : "=r"(r[0]), "=r"(r[1]), "=r"(r[2]), "=r"(r[3]) : "r"(addr));
}
__device__ __forceinline__ void mma_f16(float* c, const uint32_t* a, const uint32_t* b) {
    asm volatile(
        "mma.sync.aligned.m16n8k16.row.col.f32.f16.f16.f32 "
        "{%0,%1,%2,%3}, {%4,%5,%6,%7}, {%8,%9}, {%0,%1,%2,%3};"
        : "+f"(c[0]), "+f"(c[1]), "+f"(c[2]), "+f"(c[3])
        : "r"(a[0]), "r"(a[1]), "r"(a[2]), "r"(a[3]), "r"(b[0]), "r"(b[1]));
}
__device__ __forceinline__ float sigm(float x) { return 1.0f / (1.0f + expf(-x)); }
__device__ __forceinline__ unsigned long long enc_max(float v, int t) {
    uint32_t u = __float_as_uint(v);
    u = (u & 0x80000000u) ? ~u : (u | 0x80000000u);
    return ((unsigned long long)u << 32) | (uint32_t)(TLEN - 1 - t);
}
__device__ __forceinline__ int dec_idx(unsigned long long s) {
    return TLEN - 1 - (int)(uint32_t)(s & 0xFFFFFFFFull);
}
__device__ __forceinline__ float dot4(float4 a, float4 b) {
    return a.x * b.x + a.y * b.y + a.z * b.z + a.w * b.w;
}

// ------------------------------------------------------------------
// prep: tiled transposes (all global accesses coalesced)
// ------------------------------------------------------------------
__global__ void prep_UT(const float* __restrict__ U) {
    __shared__ float tile[32][33];
    int k0 = blockIdx.x * 32, t0 = blockIdx.y * 32;
    int tx = threadIdx.x, ty0 = threadIdx.y;
#pragma unroll
    for (int i = 0; i < 4; i++) {
        int tk = ty0 * 4 + i;
        int k = k0 + tk;
        tile[tk][tx] = (k < 2 * HD) ? U[(size_t)k * TLEN + t0 + tx] : 0.f;
    }
    __syncthreads();
#pragma unroll
    for (int i = 0; i < 4; i++) {
        int tt = ty0 * 4 + i;
        g_UT[t0 + tt][k0 + tx] = __float2half(tile[tx][tt]);
    }
}

__global__ void prep_B1(const float* __restrict__ W1a, const float* __restrict__ W1b) {
    __shared__ float tile[32][33];
    int net = blockIdx.z;
    int k0 = blockIdx.x * 32, n0 = blockIdx.y * 32;
    int tx = threadIdx.x, ty0 = threadIdx.y;
    const float* W1 = net ? W1b : W1a;
#pragma unroll
    for (int i = 0; i < 4; i++) {
        int ty = ty0 * 4 + i;
        int n = n0 + ty;
        int h = n >> 4, p = n & 15;
        int k = k0 + tx;
        tile[ty][tx] = (k < 2 * HD) ? W1[(size_t)(p * HD + h) * 600 + k] : 0.f;
    }
    __syncthreads();
#pragma unroll
    for (int i = 0; i < 4; i++) {
        int ty = ty0 * 4 + i;
        g_B1[net][k0 + ty][n0 + tx] = __float2half(tile[tx][ty]);
    }
}

__global__ void prep_B2(const float* __restrict__ W2a, const float* __restrict__ W2b) {
    __shared__ float tile[32][33];
    int net = blockIdx.z;
    int k0 = blockIdx.x * 32, n0 = blockIdx.y * 32;
    int tx = threadIdx.x, ty0 = threadIdx.y;
    const float* W2 = net ? W2b : W2a;
#pragma unroll
    for (int i = 0; i < 4; i++) {
        int ty = ty0 * 4 + i;
        int n = n0 + ty;
        int h = n >> 4, p = n & 15;
        int k = k0 + tx;
        tile[ty][tx] = (k < HD) ? W2[(size_t)(p * HD + h) * HD + k] : 0.f;
    }
    __syncthreads();
#pragma unroll
    for (int i = 0; i < 4; i++) {
        int ty = ty0 * 4 + i;
        g_B2[net][k0 + ty][n0 + tx] = __float2half(tile[tx][ty]);
    }
}

__global__ void prep_misc(const float* __restrict__ b2a, const float* __restrict__ b2b,
                          const float* __restrict__ h0,  const float* __restrict__ c0) {
    int idx0 = blockIdx.x * blockDim.x + threadIdx.x;
    int stride = gridDim.x * blockDim.x;
    for (int i = idx0; i < 2 * NPH; i += stride) {
        int net = i / NPH, n = i - net * NPH;
        int h = n >> 4, p = n & 15;
        const float* b2 = net ? b2b : b2a;
        g_b2T[net][n] = b2[p * HD + h];
    }
    for (int i = idx0; i < 2 * TLEN * (K2PAD - HD); i += stride) {
        int net = i / (TLEN * (K2PAD - HD));
        int rem = i - net * (TLEN * (K2PAD - HD));
        int t = rem / (K2PAD - HD);
        int k = HD + (rem - t * (K2PAD - HD));
        g_m1[net][t][k] = __float2half(0.f);
    }
    if (idx0 < HD) { g_hB[1][idx0] = h0[idx0]; g_cB[1][idx0] = c0[idx0]; }
}

// ------------------------------------------------------------------
// mma.sync GEMM (proven shape): C[t][n] = sum_k A[t][k]*B[k][n]
// MODE 0: A=UT (K=416), B=B1 -> fp16 store to g_PU
// MODE 1: A=m1 (K=224), B=B2 -> +b2T, max over p -> g_m2[t][h]
// Block tile 128x128, 256 threads, 8 warps (4m x 2n), warp 32x64,
// K-chunk 32, 3-stage cp.async pipeline (wait_group 1). 2 CTAs/SM.
// ------------------------------------------------------------------
#define A_ROW_B   80
#define A_STG_B   10240
#define B_ROW_B   272
#define B_STG_B   8704
#define OFF_B     30720              // 3 * A_STG_B
#define GEMM_SMEM (30720 + 26112)    // 3 A stages + 3 B stages = 56832

template <int MODE>
__global__ void __launch_bounds__(256) gemm_mma() {
    extern __shared__ char smem[];
    const int tid    = threadIdx.x;
    const int lane   = tid & 31;
    const int wid    = tid >> 5;
    const int warp_m = wid & 3;
    const int warp_n = wid >> 2;
    const int net    = blockIdx.z;
    const int m0     = blockIdx.x * 128;
    const int n0     = blockIdx.y * 128;
    const int KPAD   = (MODE == 0) ? K1PAD : K2PAD;
    const int NC     = KPAD / 32;

    const __half* __restrict__ Ap = (MODE == 0) ? &g_UT[0][0] : &g_m1[net][0][0];
    const __half* __restrict__ Bp = (MODE == 0) ? &g_B1[net][0][0] : &g_B2[net][0][0];

    const uint32_t sb = smem_u32(smem);

    const int arow = tid >> 1;
    const int aq   = (tid & 1) * 2;
    const int brow = tid >> 3;
    const int bq   = tid & 7;

    auto load_stage = [&](int stage, int kc) {
        const uint32_t as = sb + stage * A_STG_B + arow * A_ROW_B + aq * 16;
        const __half* ah = Ap + (size_t)(m0 + arow) * KPAD + kc + aq * 8;
        cp16(as,      ah);
        cp16(as + 16, ah + 8);
        const uint32_t bs = sb + OFF_B + stage * B_STG_B + brow * B_ROW_B + bq * 32;
        const __half* bg = Bp + (size_t)(kc + brow) * NPH + n0 + bq * 16;
        cp16(bs,      bg);
        cp16(bs + 16, bg + 8);
    };

    float acc[2][8][4];
#pragma unroll
    for (int i = 0; i < 2; i++)
#pragma unroll
        for (int j = 0; j < 8; j++)
#pragma unroll
            for (int q = 0; q < 4; q++) acc[i][j][q] = 0.f;

    const int l15 = lane & 15;
    const int l16 = (lane >> 4) * 8;
    const uint32_t aBase = sb + (warp_m * 32 + l15) * A_ROW_B + l16 * 2;
    const uint32_t bBase = sb + OFF_B + l15 * B_ROW_B + (warp_n * 64 + l16) * 2;

    load_stage(0, 0);
    CP_COMMIT();
    load_stage(1, 32);
    CP_COMMIT();

    for (int c = 0; c < NC; c++) {
        CP_WAIT1();
        __syncthreads();
        const int stg = c % 3;
        const uint32_t aS = aBase + stg * A_STG_B;
        const uint32_t bS = bBase + stg * B_STG_B;
#pragma unroll
        for (int s = 0; s < 2; s++) {
            uint32_t ah[2][4];
#pragma unroll
            for (int i = 0; i < 2; i++)
                ldsm4(ah[i], aS + i * 16 * A_ROW_B + s * 32);
#pragma unroll
            for (int half = 0; half < 2; half++) {
                uint32_t bb[4][2];
#pragma unroll
                for (int pr = 0; pr < 2; pr++) {
                    uint32_t r[4];
                    ldsm4t(r, bS + s * 16 * B_ROW_B + (half * 2 + pr) * 32);
                    bb[pr * 2][0] = r[0]; bb[pr * 2][1] = r[1];
                    bb[pr * 2 + 1][0] = r[2]; bb[pr * 2 + 1][1] = r[3];
                }
#pragma unroll
                for (int i = 0; i < 2; i++)
#pragma unroll
                    for (int j = 0; j < 4; j++)
                        mma_f16(acc[i][half * 4 + j], ah[i], bb[j]);
            }
        }
        if (c + 2 < NC) { load_stage((c + 2) % 3, (c + 2) * 32); }
        CP_COMMIT();
    }

    const int g4 = lane >> 2;
    const int t2 = (lane & 3) * 2;
    if (MODE == 0) {
        __half* C = &g_PU[net][0][0];
#pragma unroll
        for (int i = 0; i < 2; i++) {
            int r0 = m0 + warp_m * 32 + i * 16 + g4;
#pragma unroll
            for (int j = 0; j < 8; j++) {
                int col = n0 + warp_n * 64 + j * 8 + t2;
                *(__half2*)&C[(size_t)r0 * NPH + col] =
                    __floats2half2_rn(acc[i][j][0], acc[i][j][1]);
                *(__half2*)&C[(size_t)(r0 + 8) * NPH + col] =
                    __floats2half2_rn(acc[i][j][2], acc[i][j][3]);
            }
        }
    } else {
        float b2v[8][2];
#pragma unroll
        for (int j = 0; j < 8; j++) {
            int col = n0 + warp_n * 64 + j * 8 + t2;
            b2v[j][0] = __ldg(&g_b2T[net][col]);
            b2v[j][1] = __ldg(&g_b2T[net][col + 1]);
        }
        const int h0i = (n0 + warp_n * 64) >> 4;
#pragma unroll
        for (int i = 0; i < 2; i++) {
#pragma unroll
            for (int hh = 0; hh < 4; hh++) {
                float mlo = -3.4e38f, mhi = -3.4e38f;
#pragma unroll
                for (int jj = 0; jj < 2; jj++) {
                    int j = hh * 2 + jj;
                    mlo = fmaxf(mlo, fmaxf(acc[i][j][0] + b2v[j][0], acc[i][j][1] + b2v[j][1]));
                    mhi = fmaxf(mhi, fmaxf(acc[i][j][2] + b2v[j][0], acc[i][j][3] + b2v[j][1]));
                }
                mlo = fmaxf(mlo, __shfl_xor_sync(0xffffffffu, mlo, 1));
                mlo = fmaxf(mlo, __shfl_xor_sync(0xffffffffu, mlo, 2));
                mhi = fmaxf(mhi, __shfl_xor_sync(0xffffffffu, mhi, 1));
                mhi = fmaxf(mhi, __shfl_xor_sync(0xffffffffu, mhi, 2));
                if ((lane & 3) == 0) {
                    int row = m0 + warp_m * 32 + i * 16 + g4;
                    g_m2[net][row][h0i + hh]     = mlo;
                    g_m2[net][row + 8][h0i + hh] = mhi;
                }
            }
        }
    }
}

// ------------------------------------------------------------------
// LSTM gates: 8 rows/block, 1 warp per row; block 0 mirrors xs -> g_x
// ------------------------------------------------------------------
__global__ void lstm_gates(const float* __restrict__ U, const float* __restrict__ W_ih,
                           const float* __restrict__ W_hh, const float* __restrict__ b_ih,
                           const float* __restrict__ b_hh, int it) {
    __shared__ __align__(16) float xs[800];
    __shared__ __align__(16) float hs[HD];
    int tid = threadIdx.x;
    int s = (it == 0) ? 0 : dec_idx(g_slot[(it + 1) & 1][0]);
    int e = (it == 0) ? 0 : dec_idx(g_slot[(it + 1) & 1][1]);
    if (blockIdx.x == 0 && tid == 0) {
        g_slot[it & 1][0] = 0ull;
        g_slot[it & 1][1] = 0ull;
    }
    for (int j = tid; j < 800; j += 256) {
        float v = (j < 400) ? U[(size_t)j * TLEN + s] : U[(size_t)(j - 400) * TLEN + e];
        xs[j] = v;
        if (blockIdx.x == 0) g_x[j] = v;
    }
    const float* hprev = g_hB[(it + 1) & 1];
    for (int j = tid; j < HD; j += 256) hs[j] = hprev[j];
    __syncthreads();
    int row = blockIdx.x * 8 + (tid >> 5);
    int lane = tid & 31;
    const float4* w4  = (const float4*)&W_ih[(size_t)row * 800];
    const float4* xs4 = (const float4*)xs;
    float acc = 0.f;
    for (int k = lane; k < 200; k += 32) acc += dot4(w4[k], xs4[k]);
    const float4* wh4 = (const float4*)&W_hh[(size_t)row * HD];
    const float4* hs4 = (const float4*)hs;
    if (lane < 25) {
        acc += dot4(wh4[lane], hs4[lane]);
        acc += dot4(wh4[lane + 25], hs4[lane + 25]);
    }
#pragma unroll
    for (int o = 16; o; o >>= 1) acc += __shfl_xor_sync(0xffffffffu, acc, o);
    if (lane == 0) g_g[row] = acc + b_ih[row] + b_hh[row];
}

// ------------------------------------------------------------------
// fused LSTM update + r = tanh(WD @ [h_new, u_s, u_e]); x from g_x
// 4 rows/block, 2 warps per row (coalesced g_x makes widening safe now)
// ------------------------------------------------------------------
__global__ void r_kernel(const float* __restrict__ WDa, const float* __restrict__ WDb,
                         int it) {
    __shared__ __align__(16) float vs[1000];
    __shared__ float wsum[8];
    int tid = threadIdx.x;
    if (tid < HD) {
        float gi = g_g[tid], gf = g_g[HD + tid], gg = g_g[2 * HD + tid], go = g_g[3 * HD + tid];
        float c = sigm(gf) * g_cB[(it + 1) & 1][tid] + sigm(gi) * tanhf(gg);
        float h = sigm(go) * tanhf(c);
        vs[tid] = h;
        if (blockIdx.x == 0) { g_cB[it & 1][tid] = c; g_hB[it & 1][tid] = h; }
    }
    for (int j = tid; j < 800; j += 256) vs[HD + j] = g_x[j];
    __syncthreads();
    int row = blockIdx.x * 4 + (tid >> 6);
    int l64 = tid & 63;
    int lane = tid & 31;
    int net = row / HD;
    int rr = row - net * HD;
    const float* WD = net ? WDb : WDa;
    const float4* w4  = (const float4*)&WD[(size_t)rr * 1000];
    const float4* vs4 = (const float4*)vs;
    float acc = 0.f;
    for (int k = l64; k < 250; k += 64) acc += dot4(w4[k], vs4[k]);
#pragma unroll
    for (int o = 16; o; o >>= 1) acc += __shfl_xor_sync(0xffffffffu, acc, o);
    if (lane == 0) wsum[tid >> 5] = acc;
    __syncthreads();
    if (l64 == 0) {
        int w = tid >> 5;
        g_r[net][rr] = tanhf(wsum[w] + wsum[w + 1]);
    }
}

// ------------------------------------------------------------------
// prT[net][h*16+p] = W1r[p][h]@r + b1[p][h]; 1 output/warp, 800 blocks
// ------------------------------------------------------------------
__global__ void pr_kernel(const float* __restrict__ W1a, const float* __restrict__ W1b,
                          const float* __restrict__ b1a, const float* __restrict__ b1b) {
    int o = blockIdx.x * 8 + (threadIdx.x >> 5);
    int lane = threadIdx.x & 31;
    int net = o / NPH;
    int n = o - net * NPH;
    int h = n >> 4, p = n & 15;
    const float* W1 = net ? W1b : W1a;
    const float* b1 = net ? b1b : b1a;
    const float4* w4 = (const float4*)&W1[(size_t)(p * HD + h) * 600 + 400];
    const float4* r4 = (const float4*)g_r[net];
    float acc = 0.f;
    if (lane < 25) {
        acc += dot4(w4[lane], r4[lane]);
        acc += dot4(w4[lane + 25], r4[lane + 25]);
    }
#pragma unroll
    for (int o2 = 16; o2; o2 >>= 1) acc += __shfl_xor_sync(0xffffffffu, acc, o2);
    if (lane == 0) g_prT[net][n] = acc + b1[p * HD + h];
}

// ------------------------------------------------------------------
// m1[t][h] = max_p(PU[t][h*16+p] + prT[h*16+p]) -> single fp16
// ------------------------------------------------------------------
__global__ void m1_kernel() {
    int net = blockIdx.y;
    int t0 = blockIdx.x * 16;
    int tid = threadIdx.x;
    for (int item = tid; item < 16 * HD; item += 256) {
        int tt = item / HD, h = item - tt * HD;
        int t = t0 + tt;
        const uint4* pu4 = (const uint4*)&g_PU[net][t][h << 4];
        const float4* pr = (const float4*)&g_prT[net][h << 4];
        uint4 v0 = pu4[0], v1 = pu4[1];
        const __half2* a = (const __half2*)&v0;
        const __half2* b = (const __half2*)&v1;
        float m = -3.4e38f;
#pragma unroll
        for (int q = 0; q < 2; q++) {
            float4 pv = pr[q];
            float2 a0 = __half22float2(a[q * 2]);
            float2 a1 = __half22float2(a[q * 2 + 1]);
            m = fmaxf(m, fmaxf(fmaxf(a0.x + pv.x, a0.y + pv.y), fmaxf(a1.x + pv.z, a1.y + pv.w)));
        }
#pragma unroll
        for (int q = 0; q < 2; q++) {
            float4 pv = pr[2 + q];
            float2 a0 = __half22float2(b[q * 2]);
            float2 a1 = __half22float2(b[q * 2 + 1]);
            m = fmaxf(m, fmaxf(fmaxf(a0.x + pv.x, a0.y + pv.y), fmaxf(a1.x + pv.z, a1.y + pv.w)));
        }
        g_m1[net][t][h] = __float2half(m);
    }
}

// ------------------------------------------------------------------
// scores + fused argmax: 64 t per block, 512 threads
// ------------------------------------------------------------------
#define SCORE_SMEM ((64 * 408 + 16 * 401 + 128) * 4)
__global__ void __launch_bounds__(512) score_kernel(
        const float* __restrict__ W3a, const float* __restrict__ W3b,
        const float* __restrict__ b3a, const float* __restrict__ b3b,
        float* __restrict__ out, int it, int maxI) {
    extern __shared__ float sm[];
    float* ms  = sm;                 // [64][408]
    float* w3s = sm + 64 * 408;      // [16][401]
    float* bmx = w3s + 16 * 401;     // [64]
    int*   bmi = (int*)(bmx + 64);   // [64]
    int net = blockIdx.y;
    int t0 = blockIdx.x * 64;
    int tid = threadIdx.x;
    const float* W3 = net ? W3b : W3a;
    for (int idx = tid; idx < 6400; idx += 512) {
        int p = idx / 400, d = idx - p * 400;
        w3s[p * 401 + d] = W3[p * 400 + d];
    }
    for (int idx = tid; idx < 64 * HD; idx += 512) {
        int tt = idx / HD, h = idx - tt * HD;
        int t = t0 + tt;
        ms[tt * 408 + h] = __half2float(g_m1[net][t][h]);
        ms[tt * 408 + 200 + h] = g_m2[net][t][h];
    }
    __syncthreads();
    int grp = tid >> 4, p = tid & 15;
    float bias = (net ? b3b : b3a)[p];
    const float* w3r = &w3s[p * 401];
#pragma unroll
    for (int rep = 0; rep < 2; rep++) {
        int tt = grp + rep * 32;
        float acc = bias;
        const float* msr = &ms[tt * 408];
#pragma unroll 4
        for (int d = 0; d < 400; d++) acc = fmaf(msr[d], w3r[d], acc);
#pragma unroll
        for (int o = 8; o; o >>= 1) acc = fmaxf(acc, __shfl_xor_sync(0xffffffffu, acc, o));
        if (p == 0) {
            out[((size_t)net * maxI + it) * TLEN + t0 + tt] = acc;
            bmx[tt] = acc;
            bmi[tt] = t0 + tt;
        }
    }
    __syncthreads();
    if (tid == 0) {
        float bv = bmx[0]; int bi = bmi[0];
        for (int q = 1; q < 64; q++) {
            if (bmx[q] > bv) { bv = bmx[q]; bi = bmi[q]; }
        }
        atomicMax(&g_slot[it & 1][net], enc_max(bv, bi));
    }
}

__global__ void finalize_kernel(float* __restrict__ out, int maxI) {
    out[(size_t)2 * maxI * TLEN + 0] = (float)dec_idx(g_slot[(maxI - 1) & 1][0]);
    out[(size_t)2 * maxI * TLEN + 1] = (float)dec_idx(g_slot[(maxI - 1) & 1][1]);
}

// ------------------------------------------------------------------
// launch: two side streams (graph-capture fork/join)
//   s1: prep_UT -> prep_B1 -> gemm0        (joined before m1 @ it=0)
//   s2: prep_B2                            (joined before gemm1 @ it=0)
//   main: prep_misc -> iteration chain
// ------------------------------------------------------------------
extern "C" void kernel_launch(void* const* d_in, const int* in_sizes, int n_in,
                              void* d_out, int out_size) {
    const float* U    = (const float*)d_in[0];
    const float* h0   = (const float*)d_in[2];
    const float* c0   = (const float*)d_in[3];
    const float* W_ih = (const float*)d_in[4];
    const float* W_hh = (const float*)d_in[5];
    const float* b_ih = (const float*)d_in[6];
    const float* b_hh = (const float*)d_in[7];
    const float* WD_a = (const float*)d_in[8];
    const float* W1_a = (const float*)d_in[9];
    const float* b1_a = (const float*)d_in[10];
    const float* W2_a = (const float*)d_in[11];
    const float* b2_a = (const float*)d_in[12];
    const float* W3_a = (const float*)d_in[13];
    const float* b3_a = (const float*)d_in[14];
    const float* WD_b = (const float*)d_in[15];
    const float* W1_b = (const float*)d_in[16];
    const float* b1_b = (const float*)d_in[17];
    const float* W2_b = (const float*)d_in[18];
    const float* b2_b = (const float*)d_in[19];
    const float* W3_b = (const float*)d_in[20];
    const float* b3_b = (const float*)d_in[21];
    float* out = (float*)d_out;

    int maxI = out_size / (2 * TLEN);
    if (maxI < 1) maxI = 1;
    int write_se = (out_size >= 2 * maxI * TLEN + 2) ? 1 : 0;

    cudaFuncSetAttribute(gemm_mma<0>, cudaFuncAttributeMaxDynamicSharedMemorySize, GEMM_SMEM);
    cudaFuncSetAttribute(gemm_mma<1>, cudaFuncAttributeMaxDynamicSharedMemorySize, GEMM_SMEM);
    cudaFuncSetAttribute(score_kernel, cudaFuncAttributeMaxDynamicSharedMemorySize, SCORE_SMEM);

    cudaStream_t s1, s2;
    cudaStreamCreateWithFlags(&s1, cudaStreamNonBlocking);
    cudaStreamCreateWithFlags(&s2, cudaStreamNonBlocking);
    cudaEvent_t evFork, evG0, evB2;
    cudaEventCreateWithFlags(&evFork, cudaEventDisableTiming);
    cudaEventCreateWithFlags(&evG0, cudaEventDisableTiming);
    cudaEventCreateWithFlags(&evB2, cudaEventDisableTiming);

    // fork
    cudaEventRecord(evFork, 0);
    cudaStreamWaitEvent(s1, evFork, 0);
    cudaStreamWaitEvent(s2, evFork, 0);

    // s1: PU pipeline
    prep_UT<<<dim3(K1PAD / 32, TLEN / 32), dim3(32, 8), 0, s1>>>(U);
    prep_B1<<<dim3(K1PAD / 32, NPH / 32, 2), dim3(32, 8), 0, s1>>>(W1_a, W1_b);
    gemm_mma<0><<<dim3(TLEN / 128, NPH / 128, 2), 256, GEMM_SMEM, s1>>>();
    cudaEventRecord(evG0, s1);

    // s2: B2 build
    prep_B2<<<dim3(K2PAD / 32, NPH / 32, 2), dim3(32, 8), 0, s2>>>(W2_a, W2_b);
    cudaEventRecord(evB2, s2);

    // main: state init + iteration chain
    prep_misc<<<128, 256>>>(b2_a, b2_b, h0, c0);

    for (int it = 0; it < maxI; it++) {
        lstm_gates<<<100, 256>>>(U, W_ih, W_hh, b_ih, b_hh, it);
        r_kernel<<<100, 256>>>(WD_a, WD_b, it);
        pr_kernel<<<800, 256>>>(W1_a, W1_b, b1_a, b1_b);
        if (it == 0) cudaStreamWaitEvent(0, evG0, 0);   // join: m1 needs PU
        m1_kernel<<<dim3(TLEN / 16, 2), 256>>>();
        if (it == 0) cudaStreamWaitEvent(0, evB2, 0);   // join: gemm1 needs B2
        gemm_mma<1><<<dim3(TLEN / 128, NPH / 128, 2), 256, GEMM_SMEM>>>();
        score_kernel<<<dim3(TLEN / 64, 2), 512, SCORE_SMEM>>>(W3_a, W3_b, b3_a, b3_b, out, it, maxI);
    }
    if (write_se) finalize_kernel<<<1, 1>>>(out, maxI);

    cudaEventDestroy(evFork);
    cudaEventDestroy(evG0);
    cudaEventDestroy(evB2);
    cudaStreamDestroy(s1);
    cudaStreamDestroy(s2);
}